// round 6
// baseline (speedup 1.0000x reference)
#include <cuda_runtime.h>
#include <math.h>
#include <stdint.h>

// Problem constants
#define T_       1024
#define D_       1024
#define E_       16
#define K_SEL    4
#define NGRP     4
#define INTER_   512
#define SH_INTER 1024
#define RSCALE   2.5f

#define LDPA 40                       // A-plane padded row stride (floats) — LDS.64 conflict-free
#define LDPB 36                       // B-plane padded row stride (floats) — LDS.32 conflict-free
#define BUFA (128 * LDPA * 4)         // one A stage, bytes
#define BUFBB (128 * LDPB * 4)        // one B stage, bytes
#define NZ   18                       // 16 routed experts + 2 shared halves

// ---------------- device scratch ----------------
__device__ int   g_cnt[E_];
__device__ int   g_tok[E_ * T_];
__device__ float g_wt [E_ * T_];
__device__ float g_xr[(size_t)T_ * D_];               // tf32-rounded, column-permuted x
__device__ float g_inter[(size_t)E_ * T_ * INTER_];   // rounded+permuted SwiGLU activations
__device__ float g_hsh[(size_t)T_ * SH_INTER];        // rounded+permuted shared activations

// ---------------- helpers ----------------
__device__ __forceinline__ uint32_t smem_u32(const void* p) {
    uint32_t a;
    asm("{ .reg .u64 t; cvta.to.shared.u64 t, %1; cvt.u32.u64 %0, t; }" : "=r"(a) : "l"(p));
    return a;
}
__device__ __forceinline__ void cp16(uint32_t s, const float* g) {
    asm volatile("cp.async.cg.shared.global [%0], [%1], 16;" :: "r"(s), "l"(g) : "memory");
}
#define CP_COMMIT() asm volatile("cp.async.commit_group;" ::: "memory")
#define CP_WAIT(n)  asm volatile("cp.async.wait_group %0;" :: "n"(n) : "memory")

__device__ __forceinline__ float tf32r(float f) {
    uint32_t u;
    asm("cvt.rna.tf32.f32 %0, %1;" : "=r"(u) : "f"(f));
    return __uint_as_float(u);
}
__device__ __forceinline__ uint32_t lds_tf32(const float* p) {
    uint32_t u;
    asm("cvt.rna.tf32.f32 %0, %1;" : "=r"(u) : "f"(*p));
    return u;
}
// within each 8-column group: orig col (c + 4h), c in 0..3, h in 0..1 -> pos 2c + h
__device__ __forceinline__ int perm8(int j) {
    return (j & ~7) | (((j & 3) << 1) | ((j >> 2) & 1));
}
__device__ __forceinline__ void mma_tf32(float c[4],
                                         uint32_t a0, uint32_t a1, uint32_t a2, uint32_t a3,
                                         uint32_t b0, uint32_t b1) {
    asm volatile(
        "mma.sync.aligned.m16n8k8.row.col.f32.tf32.tf32.f32 "
        "{%0,%1,%2,%3}, {%4,%5,%6,%7}, {%8,%9}, {%0,%1,%2,%3};"
        : "+f"(c[0]), "+f"(c[1]), "+f"(c[2]), "+f"(c[3])
        : "r"(a0), "r"(a1), "r"(a2), "r"(a3), "r"(b0), "r"(b1));
}
__device__ __forceinline__ float silu_mul(float g, float u) {
    return g / (1.f + expf(-g)) * u;
}

// ---------------- routing & pre-round ----------------
__global__ void zero_counts_kernel() {
    if (threadIdx.x < E_) g_cnt[threadIdx.x] = 0;
}

__global__ void round_x_kernel(const float* __restrict__ x) {
    const int t = blockIdx.x;
    const float4* xr = (const float4*)(x + (size_t)t * D_);
    float* dst = g_xr + (size_t)t * D_;
    for (int i = threadIdx.x; i < D_ / 4; i += blockDim.x) {
        float4 v = xr[i];
        const int k = i * 4;
        dst[perm8(k + 0)] = tf32r(v.x);
        dst[perm8(k + 1)] = tf32r(v.y);
        dst[perm8(k + 2)] = tf32r(v.z);
        dst[perm8(k + 3)] = tf32r(v.w);
    }
}

__global__ void route_kernel(const float* __restrict__ x,
                             const float* __restrict__ gw,
                             const float* __restrict__ gb) {
    const int t = blockIdx.x;
    __shared__ float xs[D_];
    __shared__ float sc[E_];
    const int tid = threadIdx.x;  // 128
    const float4* xr = (const float4*)(x + (size_t)t * D_);
    float4* xs4 = (float4*)xs;
    for (int i = tid; i < D_ / 4; i += 128) xs4[i] = xr[i];
    __syncthreads();

    const int warp = tid >> 5, lane = tid & 31;
    for (int e = warp * 4; e < warp * 4 + 4; e++) {
        const float* w = gw + (size_t)e * D_;
        float p = 0.f;
        for (int j = lane; j < D_; j += 32) p += xs[j] * w[j];
        #pragma unroll
        for (int o = 16; o; o >>= 1) p += __shfl_xor_sync(0xffffffffu, p, o);
        if (lane == 0) sc[e] = 1.f / (1.f + expf(-p));
    }
    __syncthreads();

    if (tid == 0) {
        float s[E_];
        #pragma unroll
        for (int e = 0; e < E_; e++) s[e] = sc[e] + gb[e];
        float gsc[NGRP];
        #pragma unroll
        for (int g = 0; g < NGRP; g++) {
            float m1 = -1e30f, m2 = -1e30f;
            #pragma unroll
            for (int j = 0; j < 4; j++) {
                float v = s[g * 4 + j];
                if (v > m1) { m2 = m1; m1 = v; } else if (v > m2) { m2 = v; }
            }
            gsc[g] = m1 + m2;
        }
        int g1 = 0;
        for (int g = 1; g < NGRP; g++) if (gsc[g] > gsc[g1]) g1 = g;
        int g2 = -1;
        for (int g = 0; g < NGRP; g++) {
            if (g == g1) continue;
            if (g2 < 0 || gsc[g] > gsc[g2]) g2 = g;
        }
        float masked[E_];
        #pragma unroll
        for (int e = 0; e < E_; e++) {
            int g = e >> 2;
            masked[e] = (g == g1 || g == g2) ? s[e] : 0.f;
        }
        int idx[K_SEL];
        float w[K_SEL];
        bool used[E_];
        #pragma unroll
        for (int e = 0; e < E_; e++) used[e] = false;
        float wsum = 0.f;
        for (int k = 0; k < K_SEL; k++) {
            int best = -1; float bv = -1e30f;
            for (int e = 0; e < E_; e++) {
                if (used[e]) continue;
                if (masked[e] > bv) { bv = masked[e]; best = e; }
            }
            used[best] = true;
            idx[k] = best;
            w[k] = sc[best];
            wsum += w[k];
        }
        const float scale = RSCALE / wsum;
        for (int k = 0; k < K_SEL; k++) {
            int e = idx[k];
            int pos = atomicAdd(&g_cnt[e], 1);
            g_tok[e * T_ + pos] = t;
            g_wt [e * T_ + pos] = w[k] * scale;
        }
    }
}

// ================================================================
// GEMM 1 (unified): z<16 routed expert z, z>=16 shared half (z-16).
// C = silu(X Wg^T) * (X Wu^T).  Block: 128 M x 64 N (gate), dual-B.
// A = g_xr (pre-rounded, permuted): LDS.64 pairs, no CVT.
// Output written rounded + permuted for the down GEMM.
// ================================================================
__global__ void __launch_bounds__(256, 2) mma_gu_kernel(const float* __restrict__ gp,
                                                        const float* __restrict__ up,
                                                        const float* __restrict__ sg,
                                                        const float* __restrict__ su) {
    const int z = blockIdx.z;
    const bool routed = z < E_;
    const int cnt = routed ? g_cnt[z] : T_;
    const int m0  = blockIdx.y * 128;
    if (m0 >= cnt) return;
    const int n0 = blockIdx.x * 64;

    const float* Wg;
    const float* Wu;
    float* C;
    int ldc, cb;
    if (routed) {
        Wg = gp + ((size_t)z * INTER_ + n0) * D_;
        Wu = up + ((size_t)z * INTER_ + n0) * D_;
        C = g_inter + (size_t)z * T_ * INTER_;
        ldc = INTER_; cb = n0;
    } else {
        const int h = z - E_;
        Wg = sg + ((size_t)h * 512 + n0) * D_;
        Wu = su + ((size_t)h * 512 + n0) * D_;
        C = g_hsh;
        ldc = SH_INTER; cb = h * 512 + n0;
    }

    extern __shared__ float smem[];
    float* As = smem;                      // [2][128][LDPA]
    float* Bs = smem + 2 * 128 * LDPA;     // [2][128][LDPB]
    const uint32_t sA = smem_u32(As);
    const uint32_t sB = smem_u32(Bs);

    const int tid = threadIdx.x, wid = tid >> 5, lane = tid & 31;
    const int wm = wid >> 2, wn = wid & 3;

    // per-thread cp.async plan: 4 A + 4 B 16B-chunks per stage
    const float* agl[4]; const float* bgl[4];
    uint32_t sa[4], sbo[4];
    #pragma unroll
    for (int t = 0; t < 4; t++) {
        int it = tid + 256 * t;
        int row = it >> 3, c4 = it & 7;
        int mm = m0 + row; if (mm > cnt - 1) mm = cnt - 1;
        int ar = routed ? g_tok[z * T_ + mm] : mm;
        agl[t] = g_xr + (size_t)ar * D_ + c4 * 4;
        bgl[t] = ((row < 64) ? (Wg + (size_t)row * D_) : (Wu + (size_t)(row - 64) * D_)) + c4 * 4;
        sa[t]  = sA + (uint32_t)(row * LDPA + c4 * 4) * 4u;
        sbo[t] = sB + (uint32_t)(row * LDPB + c4 * 4) * 4u;
    }

    float acg[4][2][4], acu[4][2][4];
    #pragma unroll
    for (int mi = 0; mi < 4; mi++)
        #pragma unroll
        for (int nj = 0; nj < 2; nj++)
            #pragma unroll
            for (int r = 0; r < 4; r++) { acg[mi][nj][r] = 0.f; acu[mi][nj][r] = 0.f; }

    const int NS = D_ / 32;   // 32 stages
    const int q = lane >> 2, c = lane & 3;

    // prologue: fill buffer 0
    #pragma unroll
    for (int t = 0; t < 4; t++) { cp16(sa[t], agl[t]); cp16(sbo[t], bgl[t]); }
    CP_COMMIT();

    for (int s = 0; s < NS; s++) {
        if (s + 1 < NS) {
            #pragma unroll
            for (int t = 0; t < 4; t++) {
                cp16(sa[t] + ((s + 1) & 1) * BUFA,  agl[t] + (s + 1) * 32);
                cp16(sbo[t] + ((s + 1) & 1) * BUFBB, bgl[t] + (s + 1) * 32);
            }
            CP_COMMIT();
            CP_WAIT(1);
        } else {
            CP_WAIT(0);
        }
        __syncthreads();

        const float* Ab = As + (s & 1) * 128 * LDPA;
        const float* Bb = Bs + (s & 1) * 128 * LDPB;
        #pragma unroll
        for (int ks = 0; ks < 4; ks++) {
            const int kc = ks * 8 + c;       // original k index (for B)
            const int ka = ks * 8 + 2 * c;   // permuted pair position (for A)
            uint32_t af[4][4];
            #pragma unroll
            for (int mi = 0; mi < 4; mi++) {
                const int r = wm * 64 + mi * 16 + q;
                const float2 p0 = *(const float2*)(Ab + r * LDPA + ka);
                const float2 p1 = *(const float2*)(Ab + (r + 8) * LDPA + ka);
                af[mi][0] = __float_as_uint(p0.x);
                af[mi][1] = __float_as_uint(p1.x);
                af[mi][2] = __float_as_uint(p0.y);
                af[mi][3] = __float_as_uint(p1.y);
            }
            #pragma unroll
            for (int nj = 0; nj < 2; nj++) {
                const int n = wn * 16 + nj * 8 + q;
                uint32_t bg0 = lds_tf32(&Bb[n * LDPB + kc]);
                uint32_t bg1 = lds_tf32(&Bb[n * LDPB + kc + 4]);
                uint32_t bu0 = lds_tf32(&Bb[(n + 64) * LDPB + kc]);
                uint32_t bu1 = lds_tf32(&Bb[(n + 64) * LDPB + kc + 4]);
                #pragma unroll
                for (int mi = 0; mi < 4; mi++) {
                    mma_tf32(acg[mi][nj], af[mi][0], af[mi][1], af[mi][2], af[mi][3], bg0, bg1);
                    mma_tf32(acu[mi][nj], af[mi][0], af[mi][1], af[mi][2], af[mi][3], bu0, bu1);
                }
            }
        }
        __syncthreads();
    }

    // epilogue: SwiGLU; store rounded + permuted (for down GEMM's A)
    const int c2 = (lane & 3) * 2;
    #pragma unroll
    for (int mi = 0; mi < 4; mi++) {
        const int r0 = m0 + wm * 64 + mi * 16 + q;
        #pragma unroll
        for (int nj = 0; nj < 2; nj++) {
            const int col = cb + wn * 16 + nj * 8 + c2;
            const int p0 = perm8(col), p1 = perm8(col + 1);
            if (r0 < cnt) {
                float* cp = C + (size_t)r0 * ldc;
                cp[p0] = tf32r(silu_mul(acg[mi][nj][0], acu[mi][nj][0]));
                cp[p1] = tf32r(silu_mul(acg[mi][nj][1], acu[mi][nj][1]));
            }
            if (r0 + 8 < cnt) {
                float* cp = C + (size_t)(r0 + 8) * ldc;
                cp[p0] = tf32r(silu_mul(acg[mi][nj][2], acu[mi][nj][2]));
                cp[p1] = tf32r(silu_mul(acg[mi][nj][3], acu[mi][nj][3]));
            }
        }
    }
}

// ================================================================
// GEMM 2 (unified): out += w * (A Wd^T), all via atomicAdd.
// z<16: A = g_inter[z] (K=512, pre-rounded+permuted).  z>=16: shared half.
// Block 128 M x 128 N.
// ================================================================
__global__ void __launch_bounds__(256, 2) mma_down_kernel(const float* __restrict__ dp,
                                                          const float* __restrict__ sd,
                                                          float* __restrict__ out) {
    const int z = blockIdx.z;
    const bool routed = z < E_;
    const int cnt = routed ? g_cnt[z] : T_;
    const int m0  = blockIdx.y * 128;
    if (m0 >= cnt) return;
    const int n0 = blockIdx.x * 128;

    const float* A;
    const float* W;
    int lda, ldw;
    if (routed) {
        A = g_inter + (size_t)z * T_ * INTER_; lda = INTER_;
        W = dp + (size_t)z * D_ * INTER_;      ldw = INTER_;
    } else {
        const int h = z - E_;
        A = g_hsh + (size_t)h * 512; lda = SH_INTER;
        W = sd    + (size_t)h * 512; ldw = SH_INTER;
    }

    extern __shared__ float smem[];
    float* As = smem;
    float* Bs = smem + 2 * 128 * LDPA;
    const uint32_t sA = smem_u32(As);
    const uint32_t sB = smem_u32(Bs);

    const int tid = threadIdx.x, wid = tid >> 5, lane = tid & 31;
    const int wm = wid >> 2, wn = wid & 3;

    const float* agl[4]; const float* bgl[4];
    uint32_t sa[4], sbo[4];
    #pragma unroll
    for (int t = 0; t < 4; t++) {
        int it = tid + 256 * t;
        int row = it >> 3, c4 = it & 7;
        int mm = m0 + row; if (mm > cnt - 1) mm = cnt - 1;
        agl[t] = A + (size_t)mm * lda + c4 * 4;
        bgl[t] = W + (size_t)(n0 + row) * ldw + c4 * 4;
        sa[t]  = sA + (uint32_t)(row * LDPA + c4 * 4) * 4u;
        sbo[t] = sB + (uint32_t)(row * LDPB + c4 * 4) * 4u;
    }

    float acc[4][4][4];
    #pragma unroll
    for (int mi = 0; mi < 4; mi++)
        #pragma unroll
        for (int nj = 0; nj < 4; nj++)
            #pragma unroll
            for (int r = 0; r < 4; r++) acc[mi][nj][r] = 0.f;

    const int NS = INTER_ / 32;   // 16 stages
    const int q = lane >> 2, c = lane & 3;

    #pragma unroll
    for (int t = 0; t < 4; t++) { cp16(sa[t], agl[t]); cp16(sbo[t], bgl[t]); }
    CP_COMMIT();

    for (int s = 0; s < NS; s++) {
        if (s + 1 < NS) {
            #pragma unroll
            for (int t = 0; t < 4; t++) {
                cp16(sa[t] + ((s + 1) & 1) * BUFA,  agl[t] + (s + 1) * 32);
                cp16(sbo[t] + ((s + 1) & 1) * BUFBB, bgl[t] + (s + 1) * 32);
            }
            CP_COMMIT();
            CP_WAIT(1);
        } else {
            CP_WAIT(0);
        }
        __syncthreads();

        const float* Ab = As + (s & 1) * 128 * LDPA;
        const float* Bb = Bs + (s & 1) * 128 * LDPB;
        #pragma unroll
        for (int ks = 0; ks < 4; ks++) {
            const int kc = ks * 8 + c;
            const int ka = ks * 8 + 2 * c;
            uint32_t af[4][4];
            #pragma unroll
            for (int mi = 0; mi < 4; mi++) {
                const int r = wm * 64 + mi * 16 + q;
                const float2 p0 = *(const float2*)(Ab + r * LDPA + ka);
                const float2 p1 = *(const float2*)(Ab + (r + 8) * LDPA + ka);
                af[mi][0] = __float_as_uint(p0.x);
                af[mi][1] = __float_as_uint(p1.x);
                af[mi][2] = __float_as_uint(p0.y);
                af[mi][3] = __float_as_uint(p1.y);
            }
            #pragma unroll
            for (int nj = 0; nj < 4; nj++) {
                const int n = wn * 32 + nj * 8 + q;
                uint32_t b0 = lds_tf32(&Bb[n * LDPB + kc]);
                uint32_t b1 = lds_tf32(&Bb[n * LDPB + kc + 4]);
                #pragma unroll
                for (int mi = 0; mi < 4; mi++)
                    mma_tf32(acc[mi][nj], af[mi][0], af[mi][1], af[mi][2], af[mi][3], b0, b1);
            }
        }
        __syncthreads();
    }

    // epilogue: all contributions atomically accumulate (out columns unpermuted)
    const int c2 = (lane & 3) * 2;
    #pragma unroll
    for (int mi = 0; mi < 4; mi++) {
        #pragma unroll
        for (int half = 0; half < 2; half++) {
            const int m = m0 + wm * 64 + mi * 16 + q + half * 8;
            if (m >= cnt) continue;
            const int   tok = routed ? g_tok[z * T_ + m] : m;
            const float wt  = routed ? g_wt [z * T_ + m] : 1.f;
            float* op = out + (size_t)tok * D_;
            #pragma unroll
            for (int nj = 0; nj < 4; nj++) {
                const int col = n0 + wn * 32 + nj * 8 + c2;
                atomicAdd(op + col,     wt * acc[mi][nj][half * 2 + 0]);
                atomicAdd(op + col + 1, wt * acc[mi][nj][half * 2 + 1]);
            }
        }
    }
}

// ---------------- launch ----------------
#define SMEM_BYTES (2 * 128 * (LDPA + LDPB) * 4)   // 77824 B

extern "C" void kernel_launch(void* const* d_in, const int* in_sizes, int n_in,
                              void* d_out, int out_size) {
    const float* x  = (const float*)d_in[0];
    const float* gw = (const float*)d_in[2];
    const float* gb = (const float*)d_in[3];
    const float* gp = (const float*)d_in[4];
    const float* up = (const float*)d_in[5];
    const float* dp = (const float*)d_in[6];
    const float* sg = (const float*)d_in[7];
    const float* su = (const float*)d_in[8];
    const float* sd = (const float*)d_in[9];
    float* out = (float*)d_out;

    cudaFuncSetAttribute(mma_gu_kernel,   cudaFuncAttributeMaxDynamicSharedMemorySize, SMEM_BYTES);
    cudaFuncSetAttribute(mma_down_kernel, cudaFuncAttributeMaxDynamicSharedMemorySize, SMEM_BYTES);

    cudaMemsetAsync(out, 0, (size_t)T_ * D_ * sizeof(float), 0);
    zero_counts_kernel<<<1, 32>>>();
    round_x_kernel<<<T_, 256>>>(x);
    route_kernel<<<T_, 128>>>(x, gw, gb);

    mma_gu_kernel<<<dim3(8, T_ / 128, NZ), 256, SMEM_BYTES>>>(gp, up, sg, su);
    mma_down_kernel<<<dim3(D_ / 128, T_ / 128, NZ), 256, SMEM_BYTES>>>(dp, sd, out);
}

// round 7
// speedup vs baseline: 1.2542x; 1.2542x over previous
#include <cuda_runtime.h>
#include <cuda_fp16.h>
#include <math.h>
#include <stdint.h>

// Problem constants
#define T_       1024
#define D_       1024
#define E_       16
#define K_SEL    4
#define NGRP     4
#define INTER_   512
#define SH_INTER 1024
#define RSCALE   2.5f

#define LDH   40                      // smem row stride in halves (80B, conflict-free)
#define PLANE (128 * LDH)             // halves per plane-stage
#define ABYTES (PLANE * 2)            // 10240 B
#define SMEM_BYTES (4 * ABYTES)       // A0,A1,B0,B1 = 40960 B
#define NZ    18                      // 16 routed experts + 2 shared halves

// ---------------- device scratch (fp16 operands) ----------------
__device__ int    g_cnt[E_];
__device__ int    g_tok[E_ * T_];
__device__ float  g_wt [E_ * T_];
__device__ __half h_x [(size_t)T_ * D_];
__device__ __half h_gp[(size_t)E_ * INTER_ * D_];
__device__ __half h_up[(size_t)E_ * INTER_ * D_];
__device__ __half h_dp[(size_t)E_ * D_ * INTER_];
__device__ __half h_sg[(size_t)SH_INTER * D_];
__device__ __half h_su[(size_t)SH_INTER * D_];
__device__ __half h_sd[(size_t)D_ * SH_INTER];
__device__ __half g_inter[(size_t)E_ * T_ * INTER_];
__device__ __half g_hsh[(size_t)T_ * SH_INTER];

// ---------------- helpers ----------------
__device__ __forceinline__ uint32_t smem_u32(const void* p) {
    uint32_t a;
    asm("{ .reg .u64 t; cvta.to.shared.u64 t, %1; cvt.u32.u64 %0, t; }" : "=r"(a) : "l"(p));
    return a;
}
__device__ __forceinline__ void cp16(uint32_t s, const void* g) {
    asm volatile("cp.async.cg.shared.global [%0], [%1], 16;" :: "r"(s), "l"(g) : "memory");
}
#define CP_COMMIT() asm volatile("cp.async.commit_group;" ::: "memory")
#define CP_WAIT(n)  asm volatile("cp.async.wait_group %0;" :: "n"(n) : "memory")

__device__ __forceinline__ void mma_f16(float c[4],
                                        uint32_t a0, uint32_t a1, uint32_t a2, uint32_t a3,
                                        uint32_t b0, uint32_t b1) {
    asm volatile(
        "mma.sync.aligned.m16n8k16.row.col.f32.f16.f16.f32 "
        "{%0,%1,%2,%3}, {%4,%5,%6,%7}, {%8,%9}, {%0,%1,%2,%3};"
        : "+f"(c[0]), "+f"(c[1]), "+f"(c[2]), "+f"(c[3])
        : "r"(a0), "r"(a1), "r"(a2), "r"(a3), "r"(b0), "r"(b1));
}
__device__ __forceinline__ float silu_mul(float g, float u) {
    return g / (1.f + expf(-g)) * u;
}

// ---------------- fp32 -> fp16 conversion ----------------
__global__ void cvt_kernel(__half* __restrict__ dst, const float* __restrict__ src, int n4) {
    int i = blockIdx.x * blockDim.x + threadIdx.x;
    if (i < n4) {
        float4 v = ((const float4*)src)[i];
        __half2 h0 = __floats2half2_rn(v.x, v.y);
        __half2 h1 = __floats2half2_rn(v.z, v.w);
        ((__half2*)dst)[2 * i]     = h0;
        ((__half2*)dst)[2 * i + 1] = h1;
    }
}

// ---------------- routing ----------------
__global__ void zero_counts_kernel() {
    if (threadIdx.x < E_) g_cnt[threadIdx.x] = 0;
}

__global__ void route_kernel(const float* __restrict__ x,
                             const float* __restrict__ gw,
                             const float* __restrict__ gb) {
    const int t = blockIdx.x;
    __shared__ float xs[D_];
    __shared__ float sc[E_];
    const int tid = threadIdx.x;  // 128
    const float4* xr = (const float4*)(x + (size_t)t * D_);
    float4* xs4 = (float4*)xs;
    for (int i = tid; i < D_ / 4; i += 128) xs4[i] = xr[i];
    __syncthreads();

    const int warp = tid >> 5, lane = tid & 31;
    for (int e = warp * 4; e < warp * 4 + 4; e++) {
        const float* w = gw + (size_t)e * D_;
        float p = 0.f;
        for (int j = lane; j < D_; j += 32) p += xs[j] * w[j];
        #pragma unroll
        for (int o = 16; o; o >>= 1) p += __shfl_xor_sync(0xffffffffu, p, o);
        if (lane == 0) sc[e] = 1.f / (1.f + expf(-p));
    }
    __syncthreads();

    if (tid == 0) {
        float s[E_];
        #pragma unroll
        for (int e = 0; e < E_; e++) s[e] = sc[e] + gb[e];
        float gsc[NGRP];
        #pragma unroll
        for (int g = 0; g < NGRP; g++) {
            float m1 = -1e30f, m2 = -1e30f;
            #pragma unroll
            for (int j = 0; j < 4; j++) {
                float v = s[g * 4 + j];
                if (v > m1) { m2 = m1; m1 = v; } else if (v > m2) { m2 = v; }
            }
            gsc[g] = m1 + m2;
        }
        int g1 = 0;
        for (int g = 1; g < NGRP; g++) if (gsc[g] > gsc[g1]) g1 = g;
        int g2 = -1;
        for (int g = 0; g < NGRP; g++) {
            if (g == g1) continue;
            if (g2 < 0 || gsc[g] > gsc[g2]) g2 = g;
        }
        float masked[E_];
        #pragma unroll
        for (int e = 0; e < E_; e++) {
            int g = e >> 2;
            masked[e] = (g == g1 || g == g2) ? s[e] : 0.f;
        }
        int idx[K_SEL];
        float w[K_SEL];
        bool used[E_];
        #pragma unroll
        for (int e = 0; e < E_; e++) used[e] = false;
        float wsum = 0.f;
        for (int k = 0; k < K_SEL; k++) {
            int best = -1; float bv = -1e30f;
            for (int e = 0; e < E_; e++) {
                if (used[e]) continue;
                if (masked[e] > bv) { bv = masked[e]; best = e; }
            }
            used[best] = true;
            idx[k] = best;
            w[k] = sc[best];
            wsum += w[k];
        }
        const float scale = RSCALE / wsum;
        for (int k = 0; k < K_SEL; k++) {
            int e = idx[k];
            int pos = atomicAdd(&g_cnt[e], 1);
            g_tok[e * T_ + pos] = t;
            g_wt [e * T_ + pos] = w[k] * scale;
        }
    }
}

// ================================================================
// GEMM 1 (fp16): z<16 routed expert z, z>=16 shared half (z-16).
// C = silu(X Wg^T) * (X Wu^T).  Block: 128 M x 64 N (gate), dual-B.
// ================================================================
__global__ void __launch_bounds__(256, 2) mma_gu_kernel() {
    const int z = blockIdx.z;
    const bool routed = z < E_;
    const int cnt = routed ? g_cnt[z] : T_;
    const int m0  = blockIdx.y * 128;
    if (m0 >= cnt) return;
    const int n0 = blockIdx.x * 64;

    const __half* Wg;
    const __half* Wu;
    __half* C;
    int ldc, cb;
    if (routed) {
        Wg = h_gp + ((size_t)z * INTER_ + n0) * D_;
        Wu = h_up + ((size_t)z * INTER_ + n0) * D_;
        C = g_inter + (size_t)z * T_ * INTER_;
        ldc = INTER_; cb = n0;
    } else {
        const int h = z - E_;
        Wg = h_sg + ((size_t)h * 512 + n0) * D_;
        Wu = h_su + ((size_t)h * 512 + n0) * D_;
        C = g_hsh;
        ldc = SH_INTER; cb = h * 512 + n0;
    }

    extern __shared__ __half smem[];
    __half* As = smem;                 // [2][128][LDH]
    __half* Bs = smem + 2 * PLANE;     // [2][128][LDH]
    const uint32_t sA = smem_u32(As);
    const uint32_t sB = smem_u32(Bs);

    const int tid = threadIdx.x, wid = tid >> 5, lane = tid & 31;
    const int wm = wid >> 2, wn = wid & 3;

    // cp.async plan: per thread, 2 A + 2 B 16B-chunks (8 halves) per 32-K stage
    const __half* agl[2]; const __half* bgl[2];
    uint32_t sa[2], sbo[2];
    #pragma unroll
    for (int t = 0; t < 2; t++) {
        int it = tid + 256 * t;           // 0..511
        int row = it >> 2, c4 = it & 3;   // 4 chunks of 8 halves per row
        int mm = m0 + row; if (mm > cnt - 1) mm = cnt - 1;
        int ar = routed ? g_tok[z * T_ + mm] : mm;
        agl[t] = h_x + (size_t)ar * D_ + c4 * 8;
        bgl[t] = ((row < 64) ? (Wg + (size_t)row * D_) : (Wu + (size_t)(row - 64) * D_)) + c4 * 8;
        sa[t]  = sA + (uint32_t)(row * LDH + c4 * 8) * 2u;
        sbo[t] = sB + (uint32_t)(row * LDH + c4 * 8) * 2u;
    }

    float acg[4][2][4], acu[4][2][4];
    #pragma unroll
    for (int mi = 0; mi < 4; mi++)
        #pragma unroll
        for (int nj = 0; nj < 2; nj++)
            #pragma unroll
            for (int r = 0; r < 4; r++) { acg[mi][nj][r] = 0.f; acu[mi][nj][r] = 0.f; }

    const int NS = D_ / 32;   // 32 stages
    const int q = lane >> 2, c = lane & 3;

    #pragma unroll
    for (int t = 0; t < 2; t++) { cp16(sa[t], agl[t]); cp16(sbo[t], bgl[t]); }
    CP_COMMIT();

    for (int s = 0; s < NS; s++) {
        if (s + 1 < NS) {
            const uint32_t bo = (uint32_t)(((s + 1) & 1) * ABYTES);
            #pragma unroll
            for (int t = 0; t < 2; t++) {
                cp16(sa[t] + bo, agl[t] + (s + 1) * 32);
                cp16(sbo[t] + bo, bgl[t] + (s + 1) * 32);
            }
            CP_COMMIT();
            CP_WAIT(1);
        } else {
            CP_WAIT(0);
        }
        __syncthreads();

        const __half* Ab = As + (s & 1) * PLANE;
        const __half* Bb = Bs + (s & 1) * PLANE;
        #pragma unroll
        for (int ks = 0; ks < 2; ks++) {
            const int k0 = ks * 16 + 2 * c;
            uint32_t af[4][4];
            #pragma unroll
            for (int mi = 0; mi < 4; mi++) {
                const int r = wm * 64 + mi * 16 + q;
                af[mi][0] = *(const uint32_t*)(Ab + r * LDH + k0);
                af[mi][1] = *(const uint32_t*)(Ab + (r + 8) * LDH + k0);
                af[mi][2] = *(const uint32_t*)(Ab + r * LDH + k0 + 8);
                af[mi][3] = *(const uint32_t*)(Ab + (r + 8) * LDH + k0 + 8);
            }
            #pragma unroll
            for (int nj = 0; nj < 2; nj++) {
                const int n = wn * 16 + nj * 8 + q;
                uint32_t bg0 = *(const uint32_t*)(Bb + n * LDH + k0);
                uint32_t bg1 = *(const uint32_t*)(Bb + n * LDH + k0 + 8);
                uint32_t bu0 = *(const uint32_t*)(Bb + (n + 64) * LDH + k0);
                uint32_t bu1 = *(const uint32_t*)(Bb + (n + 64) * LDH + k0 + 8);
                #pragma unroll
                for (int mi = 0; mi < 4; mi++) {
                    mma_f16(acg[mi][nj], af[mi][0], af[mi][1], af[mi][2], af[mi][3], bg0, bg1);
                    mma_f16(acu[mi][nj], af[mi][0], af[mi][1], af[mi][2], af[mi][3], bu0, bu1);
                }
            }
        }
        __syncthreads();
    }

    // epilogue: SwiGLU -> fp16 C
    const int c2 = (lane & 3) * 2;
    #pragma unroll
    for (int mi = 0; mi < 4; mi++) {
        const int r0 = m0 + wm * 64 + mi * 16 + q;
        #pragma unroll
        for (int nj = 0; nj < 2; nj++) {
            const int col = cb + wn * 16 + nj * 8 + c2;
            if (r0 < cnt) {
                *(__half2*)(C + (size_t)r0 * ldc + col) =
                    __floats2half2_rn(silu_mul(acg[mi][nj][0], acu[mi][nj][0]),
                                      silu_mul(acg[mi][nj][1], acu[mi][nj][1]));
            }
            if (r0 + 8 < cnt) {
                *(__half2*)(C + (size_t)(r0 + 8) * ldc + col) =
                    __floats2half2_rn(silu_mul(acg[mi][nj][2], acu[mi][nj][2]),
                                      silu_mul(acg[mi][nj][3], acu[mi][nj][3]));
            }
        }
    }
}

// ================================================================
// GEMM 2 (fp16): out += w * (A Wd^T), all via atomicAdd.
// Block 128 M x 128 N.
// ================================================================
__global__ void __launch_bounds__(256, 2) mma_down_kernel(float* __restrict__ out) {
    const int z = blockIdx.z;
    const bool routed = z < E_;
    const int cnt = routed ? g_cnt[z] : T_;
    const int m0  = blockIdx.y * 128;
    if (m0 >= cnt) return;
    const int n0 = blockIdx.x * 128;

    const __half* A;
    const __half* W;
    int lda, ldw;
    if (routed) {
        A = g_inter + (size_t)z * T_ * INTER_; lda = INTER_;
        W = h_dp + (size_t)z * D_ * INTER_;    ldw = INTER_;
    } else {
        const int h = z - E_;
        A = g_hsh + (size_t)h * 512; lda = SH_INTER;
        W = h_sd  + (size_t)h * 512; ldw = SH_INTER;
    }

    extern __shared__ __half smem[];
    __half* As = smem;
    __half* Bs = smem + 2 * PLANE;
    const uint32_t sA = smem_u32(As);
    const uint32_t sB = smem_u32(Bs);

    const int tid = threadIdx.x, wid = tid >> 5, lane = tid & 31;
    const int wm = wid >> 2, wn = wid & 3;

    const __half* agl[2]; const __half* bgl[2];
    uint32_t sa[2], sbo[2];
    #pragma unroll
    for (int t = 0; t < 2; t++) {
        int it = tid + 256 * t;
        int row = it >> 2, c4 = it & 3;
        int mm = m0 + row; if (mm > cnt - 1) mm = cnt - 1;
        agl[t] = A + (size_t)mm * lda + c4 * 8;
        bgl[t] = W + (size_t)(n0 + row) * ldw + c4 * 8;
        sa[t]  = sA + (uint32_t)(row * LDH + c4 * 8) * 2u;
        sbo[t] = sB + (uint32_t)(row * LDH + c4 * 8) * 2u;
    }

    float acc[4][4][4];
    #pragma unroll
    for (int mi = 0; mi < 4; mi++)
        #pragma unroll
        for (int nj = 0; nj < 4; nj++)
            #pragma unroll
            for (int r = 0; r < 4; r++) acc[mi][nj][r] = 0.f;

    const int NS = INTER_ / 32;   // 16 stages
    const int q = lane >> 2, c = lane & 3;

    #pragma unroll
    for (int t = 0; t < 2; t++) { cp16(sa[t], agl[t]); cp16(sbo[t], bgl[t]); }
    CP_COMMIT();

    for (int s = 0; s < NS; s++) {
        if (s + 1 < NS) {
            const uint32_t bo = (uint32_t)(((s + 1) & 1) * ABYTES);
            #pragma unroll
            for (int t = 0; t < 2; t++) {
                cp16(sa[t] + bo, agl[t] + (s + 1) * 32);
                cp16(sbo[t] + bo, bgl[t] + (s + 1) * 32);
            }
            CP_COMMIT();
            CP_WAIT(1);
        } else {
            CP_WAIT(0);
        }
        __syncthreads();

        const __half* Ab = As + (s & 1) * PLANE;
        const __half* Bb = Bs + (s & 1) * PLANE;
        #pragma unroll
        for (int ks = 0; ks < 2; ks++) {
            const int k0 = ks * 16 + 2 * c;
            uint32_t af[4][4];
            #pragma unroll
            for (int mi = 0; mi < 4; mi++) {
                const int r = wm * 64 + mi * 16 + q;
                af[mi][0] = *(const uint32_t*)(Ab + r * LDH + k0);
                af[mi][1] = *(const uint32_t*)(Ab + (r + 8) * LDH + k0);
                af[mi][2] = *(const uint32_t*)(Ab + r * LDH + k0 + 8);
                af[mi][3] = *(const uint32_t*)(Ab + (r + 8) * LDH + k0 + 8);
            }
            #pragma unroll
            for (int nj = 0; nj < 4; nj++) {
                const int n = wn * 32 + nj * 8 + q;
                uint32_t b0 = *(const uint32_t*)(Bb + n * LDH + k0);
                uint32_t b1 = *(const uint32_t*)(Bb + n * LDH + k0 + 8);
                #pragma unroll
                for (int mi = 0; mi < 4; mi++)
                    mma_f16(acc[mi][nj], af[mi][0], af[mi][1], af[mi][2], af[mi][3], b0, b1);
            }
        }
        __syncthreads();
    }

    const int c2 = (lane & 3) * 2;
    #pragma unroll
    for (int mi = 0; mi < 4; mi++) {
        #pragma unroll
        for (int half_ = 0; half_ < 2; half_++) {
            const int m = m0 + wm * 64 + mi * 16 + q + half_ * 8;
            if (m >= cnt) continue;
            const int   tok = routed ? g_tok[z * T_ + m] : m;
            const float wt  = routed ? g_wt [z * T_ + m] : 1.f;
            float* op = out + (size_t)tok * D_;
            #pragma unroll
            for (int nj = 0; nj < 4; nj++) {
                const int col = n0 + wn * 32 + nj * 8 + c2;
                atomicAdd(op + col,     wt * acc[mi][nj][half_ * 2 + 0]);
                atomicAdd(op + col + 1, wt * acc[mi][nj][half_ * 2 + 1]);
            }
        }
    }
}

// ---------------- launch ----------------
extern "C" void kernel_launch(void* const* d_in, const int* in_sizes, int n_in,
                              void* d_out, int out_size) {
    const float* x  = (const float*)d_in[0];
    const float* gw = (const float*)d_in[2];
    const float* gb = (const float*)d_in[3];
    const float* gp = (const float*)d_in[4];
    const float* up = (const float*)d_in[5];
    const float* dp = (const float*)d_in[6];
    const float* sg = (const float*)d_in[7];
    const float* su = (const float*)d_in[8];
    const float* sd = (const float*)d_in[9];
    float* out = (float*)d_out;

    cudaFuncSetAttribute(mma_gu_kernel,   cudaFuncAttributeMaxDynamicSharedMemorySize, SMEM_BYTES);
    cudaFuncSetAttribute(mma_down_kernel, cudaFuncAttributeMaxDynamicSharedMemorySize, SMEM_BYTES);

    // resolve device-scratch addresses (host side, graph-safe)
    __half *p_x, *p_gp, *p_up, *p_dp, *p_sg, *p_su, *p_sd;
    cudaGetSymbolAddress((void**)&p_x,  h_x);
    cudaGetSymbolAddress((void**)&p_gp, h_gp);
    cudaGetSymbolAddress((void**)&p_up, h_up);
    cudaGetSymbolAddress((void**)&p_dp, h_dp);
    cudaGetSymbolAddress((void**)&p_sg, h_sg);
    cudaGetSymbolAddress((void**)&p_su, h_su);
    cudaGetSymbolAddress((void**)&p_sd, h_sd);

    cudaMemsetAsync(out, 0, (size_t)T_ * D_ * sizeof(float), 0);
    zero_counts_kernel<<<1, 32>>>();

    const int NB = 256;
    cvt_kernel<<<(T_ * D_ / 4 + NB - 1) / NB, NB>>>(p_x, x, T_ * D_ / 4);
    cvt_kernel<<<(E_ * INTER_ * D_ / 4 + NB - 1) / NB, NB>>>(p_gp, gp, E_ * INTER_ * D_ / 4);
    cvt_kernel<<<(E_ * INTER_ * D_ / 4 + NB - 1) / NB, NB>>>(p_up, up, E_ * INTER_ * D_ / 4);
    cvt_kernel<<<(E_ * D_ * INTER_ / 4 + NB - 1) / NB, NB>>>(p_dp, dp, E_ * D_ * INTER_ / 4);
    cvt_kernel<<<(SH_INTER * D_ / 4 + NB - 1) / NB, NB>>>(p_sg, sg, SH_INTER * D_ / 4);
    cvt_kernel<<<(SH_INTER * D_ / 4 + NB - 1) / NB, NB>>>(p_su, su, SH_INTER * D_ / 4);
    cvt_kernel<<<(D_ * SH_INTER / 4 + NB - 1) / NB, NB>>>(p_sd, sd, D_ * SH_INTER / 4);

    route_kernel<<<T_, 128>>>(x, gw, gb);

    mma_gu_kernel<<<dim3(8, T_ / 128, NZ), 256, SMEM_BYTES>>>();
    mma_down_kernel<<<dim3(D_ / 128, T_ / 128, NZ), 256, SMEM_BYTES>>>(out);
}

// round 8
// speedup vs baseline: 1.3485x; 1.0752x over previous
#include <cuda_runtime.h>
#include <cuda_fp16.h>
#include <math.h>
#include <stdint.h>

// Problem constants
#define T_       1024
#define D_       1024
#define E_       16
#define K_SEL    4
#define NGRP     4
#define INTER_   512
#define SH_INTER 1024
#define RSCALE   2.5f

#define LDH   40                      // smem row stride in halves (80B, LDSM conflict-free)
#define PLANE (128 * LDH)             // halves per plane-stage
#define ABYTES (PLANE * 2)            // 10240 B
#define SMEM_BYTES (4 * ABYTES)       // A0,A1,B0,B1 = 40960 B
#define NZ    18                      // 16 routed experts + 2 shared halves

// ---------------- device scratch (fp16 operands) ----------------
__device__ int    g_cnt[E_];
__device__ int    g_tok[E_ * T_];
__device__ float  g_wt [E_ * T_];
__device__ __half h_x [(size_t)T_ * D_];
__device__ __half h_gp[(size_t)E_ * INTER_ * D_];
__device__ __half h_up[(size_t)E_ * INTER_ * D_];
__device__ __half h_dp[(size_t)E_ * D_ * INTER_];
__device__ __half h_sg[(size_t)SH_INTER * D_];
__device__ __half h_su[(size_t)SH_INTER * D_];
__device__ __half h_sd[(size_t)D_ * SH_INTER];
__device__ __half g_inter[(size_t)E_ * T_ * INTER_];
__device__ __half g_hsh[(size_t)T_ * SH_INTER];

// ---------------- helpers ----------------
__device__ __forceinline__ uint32_t smem_u32(const void* p) {
    uint32_t a;
    asm("{ .reg .u64 t; cvta.to.shared.u64 t, %1; cvt.u32.u64 %0, t; }" : "=r"(a) : "l"(p));
    return a;
}
__device__ __forceinline__ void cp16(uint32_t s, const void* g) {
    asm volatile("cp.async.cg.shared.global [%0], [%1], 16;" :: "r"(s), "l"(g) : "memory");
}
#define CP_COMMIT() asm volatile("cp.async.commit_group;" ::: "memory")
#define CP_WAIT(n)  asm volatile("cp.async.wait_group %0;" :: "n"(n) : "memory")

__device__ __forceinline__ void ldsm4(uint32_t& r0, uint32_t& r1, uint32_t& r2, uint32_t& r3,
                                      uint32_t addr) {
    asm volatile("ldmatrix.sync.aligned.m8n8.x4.shared.b16 {%0,%1,%2,%3}, [%4];"
                 : "=r"(r0), "=r"(r1), "=r"(r2), "=r"(r3) : "r"(addr));
}
__device__ __forceinline__ void mma_f16(float c[4],
                                        uint32_t a0, uint32_t a1, uint32_t a2, uint32_t a3,
                                        uint32_t b0, uint32_t b1) {
    asm volatile(
        "mma.sync.aligned.m16n8k16.row.col.f32.f16.f16.f32 "
        "{%0,%1,%2,%3}, {%4,%5,%6,%7}, {%8,%9}, {%0,%1,%2,%3};"
        : "+f"(c[0]), "+f"(c[1]), "+f"(c[2]), "+f"(c[3])
        : "r"(a0), "r"(a1), "r"(a2), "r"(a3), "r"(b0), "r"(b1));
}
__device__ __forceinline__ float silu_mul(float g, float u) {
    return g / (1.f + expf(-g)) * u;
}

// ---------------- fp32 -> fp16 conversion ----------------
__global__ void cvt_kernel(__half* __restrict__ dst, const float* __restrict__ src, int n8) {
    int i = blockIdx.x * blockDim.x + threadIdx.x;
    if (i < n8) {
        float4 v0 = ((const float4*)src)[2 * i];
        float4 v1 = ((const float4*)src)[2 * i + 1];
        ((__half2*)dst)[4 * i + 0] = __floats2half2_rn(v0.x, v0.y);
        ((__half2*)dst)[4 * i + 1] = __floats2half2_rn(v0.z, v0.w);
        ((__half2*)dst)[4 * i + 2] = __floats2half2_rn(v1.x, v1.y);
        ((__half2*)dst)[4 * i + 3] = __floats2half2_rn(v1.z, v1.w);
    }
}
// fused convert for the 3 big expert-weight tensors (same size each)
__global__ void cvt3_kernel(__half* d0, const float* s0,
                            __half* d1, const float* s1,
                            __half* d2, const float* s2, int n8each) {
    int i = blockIdx.x * blockDim.x + threadIdx.x;
    const float* s; __half* d;
    if (i < n8each)            { s = s0; d = d0; }
    else if (i < 2 * n8each)   { s = s1; d = d1; i -= n8each; }
    else if (i < 3 * n8each)   { s = s2; d = d2; i -= 2 * n8each; }
    else return;
    float4 v0 = ((const float4*)s)[2 * i];
    float4 v1 = ((const float4*)s)[2 * i + 1];
    ((__half2*)d)[4 * i + 0] = __floats2half2_rn(v0.x, v0.y);
    ((__half2*)d)[4 * i + 1] = __floats2half2_rn(v0.z, v0.w);
    ((__half2*)d)[4 * i + 2] = __floats2half2_rn(v1.x, v1.y);
    ((__half2*)d)[4 * i + 3] = __floats2half2_rn(v1.z, v1.w);
}

// ---------------- routing ----------------
__global__ void zero_counts_kernel() {
    if (threadIdx.x < E_) g_cnt[threadIdx.x] = 0;
}

__global__ void route_kernel(const float* __restrict__ x,
                             const float* __restrict__ gw,
                             const float* __restrict__ gb) {
    const int t = blockIdx.x;
    __shared__ float xs[D_];
    __shared__ float sc[E_];
    const int tid = threadIdx.x;  // 128
    const float4* xr = (const float4*)(x + (size_t)t * D_);
    float4* xs4 = (float4*)xs;
    for (int i = tid; i < D_ / 4; i += 128) xs4[i] = xr[i];
    __syncthreads();

    const int warp = tid >> 5, lane = tid & 31;
    for (int e = warp * 4; e < warp * 4 + 4; e++) {
        const float* w = gw + (size_t)e * D_;
        float p = 0.f;
        for (int j = lane; j < D_; j += 32) p += xs[j] * w[j];
        #pragma unroll
        for (int o = 16; o; o >>= 1) p += __shfl_xor_sync(0xffffffffu, p, o);
        if (lane == 0) sc[e] = 1.f / (1.f + expf(-p));
    }
    __syncthreads();

    if (tid == 0) {
        float s[E_];
        #pragma unroll
        for (int e = 0; e < E_; e++) s[e] = sc[e] + gb[e];
        float gsc[NGRP];
        #pragma unroll
        for (int g = 0; g < NGRP; g++) {
            float m1 = -1e30f, m2 = -1e30f;
            #pragma unroll
            for (int j = 0; j < 4; j++) {
                float v = s[g * 4 + j];
                if (v > m1) { m2 = m1; m1 = v; } else if (v > m2) { m2 = v; }
            }
            gsc[g] = m1 + m2;
        }
        int g1 = 0;
        for (int g = 1; g < NGRP; g++) if (gsc[g] > gsc[g1]) g1 = g;
        int g2 = -1;
        for (int g = 0; g < NGRP; g++) {
            if (g == g1) continue;
            if (g2 < 0 || gsc[g] > gsc[g2]) g2 = g;
        }
        float masked[E_];
        #pragma unroll
        for (int e = 0; e < E_; e++) {
            int g = e >> 2;
            masked[e] = (g == g1 || g == g2) ? s[e] : 0.f;
        }
        int idx[K_SEL];
        float w[K_SEL];
        bool used[E_];
        #pragma unroll
        for (int e = 0; e < E_; e++) used[e] = false;
        float wsum = 0.f;
        for (int k = 0; k < K_SEL; k++) {
            int best = -1; float bv = -1e30f;
            for (int e = 0; e < E_; e++) {
                if (used[e]) continue;
                if (masked[e] > bv) { bv = masked[e]; best = e; }
            }
            used[best] = true;
            idx[k] = best;
            w[k] = sc[best];
            wsum += w[k];
        }
        const float scale = RSCALE / wsum;
        for (int k = 0; k < K_SEL; k++) {
            int e = idx[k];
            int pos = atomicAdd(&g_cnt[e], 1);
            g_tok[e * T_ + pos] = t;
            g_wt [e * T_ + pos] = w[k] * scale;
        }
    }
}

// ================================================================
// GEMM 1 (fp16 + ldmatrix): z<16 routed expert z, z>=16 shared half.
// C = silu(X Wg^T) * (X Wu^T).  Block: 128 M x 64 N (gate), dual-B.
// ================================================================
__global__ void __launch_bounds__(256, 2) mma_gu_kernel() {
    const int z = blockIdx.z;
    const bool routed = z < E_;
    const int cnt = routed ? g_cnt[z] : T_;
    const int m0  = blockIdx.y * 128;
    if (m0 >= cnt) return;
    const int n0 = blockIdx.x * 64;

    const __half* Wg;
    const __half* Wu;
    __half* C;
    int ldc, cb;
    if (routed) {
        Wg = h_gp + ((size_t)z * INTER_ + n0) * D_;
        Wu = h_up + ((size_t)z * INTER_ + n0) * D_;
        C = g_inter + (size_t)z * T_ * INTER_;
        ldc = INTER_; cb = n0;
    } else {
        const int h = z - E_;
        Wg = h_sg + ((size_t)h * 512 + n0) * D_;
        Wu = h_su + ((size_t)h * 512 + n0) * D_;
        C = g_hsh;
        ldc = SH_INTER; cb = h * 512 + n0;
    }

    extern __shared__ __half smem[];
    __half* As = smem;                 // [2][128][LDH]
    __half* Bs = smem + 2 * PLANE;     // [2][128][LDH]
    const uint32_t sA = smem_u32(As);
    const uint32_t sB = smem_u32(Bs);

    const int tid = threadIdx.x, wid = tid >> 5, lane = tid & 31;
    const int wm = wid >> 2, wn = wid & 3;

    // cp.async plan: per thread, 2 A + 2 B 16B-chunks (8 halves) per 32-K stage
    const __half* agl[2]; const __half* bgl[2];
    uint32_t sa[2], sbo[2];
    #pragma unroll
    for (int t = 0; t < 2; t++) {
        int it = tid + 256 * t;           // 0..511
        int row = it >> 2, c4 = it & 3;
        int mm = m0 + row; if (mm > cnt - 1) mm = cnt - 1;
        int ar = routed ? g_tok[z * T_ + mm] : mm;
        agl[t] = h_x + (size_t)ar * D_ + c4 * 8;
        bgl[t] = ((row < 64) ? (Wg + (size_t)row * D_) : (Wu + (size_t)(row - 64) * D_)) + c4 * 8;
        sa[t]  = sA + (uint32_t)(row * LDH + c4 * 8) * 2u;
        sbo[t] = sB + (uint32_t)(row * LDH + c4 * 8) * 2u;
    }

    // LDSM lane addressing
    // A: lanes 0-15 -> rows +0..15 at k0; lanes 16-31 -> same rows at k0+8
    const int alr = lane & 15, alk = (lane >> 4) * 8;
    const uint32_t a_lsm = sA + (uint32_t)(((wm * 64 + alr) * LDH) + alk) * 2u;
    // B: n = base + ((lane>>4)*8) + (lane&7); k = ((lane>>3)&1)*8
    const int bnr = ((lane >> 4) & 1) * 8 + (lane & 7), bkc = ((lane >> 3) & 1) * 8;
    const uint32_t bg_lsm = sB + (uint32_t)(((wn * 16 + bnr) * LDH) + bkc) * 2u;
    const uint32_t bu_lsm = sB + (uint32_t)(((wn * 16 + bnr + 64) * LDH) + bkc) * 2u;

    float acg[4][2][4], acu[4][2][4];
    #pragma unroll
    for (int mi = 0; mi < 4; mi++)
        #pragma unroll
        for (int nj = 0; nj < 2; nj++)
            #pragma unroll
            for (int r = 0; r < 4; r++) { acg[mi][nj][r] = 0.f; acu[mi][nj][r] = 0.f; }

    const int NS = D_ / 32;   // 32 stages

    #pragma unroll
    for (int t = 0; t < 2; t++) { cp16(sa[t], agl[t]); cp16(sbo[t], bgl[t]); }
    CP_COMMIT();

    for (int s = 0; s < NS; s++) {
        if (s + 1 < NS) {
            const uint32_t bo = (uint32_t)(((s + 1) & 1) * ABYTES);
            #pragma unroll
            for (int t = 0; t < 2; t++) {
                cp16(sa[t] + bo, agl[t] + (s + 1) * 32);
                cp16(sbo[t] + bo, bgl[t] + (s + 1) * 32);
            }
            CP_COMMIT();
            CP_WAIT(1);
        } else {
            CP_WAIT(0);
        }
        __syncthreads();

        const uint32_t po = (uint32_t)((s & 1) * ABYTES);
        #pragma unroll
        for (int ks = 0; ks < 2; ks++) {
            const uint32_t ko = (uint32_t)(ks * 32);   // 16 halves
            uint32_t af[4][4];
            #pragma unroll
            for (int mi = 0; mi < 4; mi++)
                ldsm4(af[mi][0], af[mi][1], af[mi][2], af[mi][3],
                      a_lsm + po + ko + (uint32_t)(mi * 16 * LDH * 2));
            uint32_t bg0a, bg1a, bg0b, bg1b, bu0a, bu1a, bu0b, bu1b;
            ldsm4(bg0a, bg1a, bg0b, bg1b, bg_lsm + po + ko);
            ldsm4(bu0a, bu1a, bu0b, bu1b, bu_lsm + po + ko);
            #pragma unroll
            for (int mi = 0; mi < 4; mi++) {
                mma_f16(acg[mi][0], af[mi][0], af[mi][1], af[mi][2], af[mi][3], bg0a, bg1a);
                mma_f16(acg[mi][1], af[mi][0], af[mi][1], af[mi][2], af[mi][3], bg0b, bg1b);
                mma_f16(acu[mi][0], af[mi][0], af[mi][1], af[mi][2], af[mi][3], bu0a, bu1a);
                mma_f16(acu[mi][1], af[mi][0], af[mi][1], af[mi][2], af[mi][3], bu0b, bu1b);
            }
        }
        __syncthreads();
    }

    // epilogue: SwiGLU -> fp16 C
    const int q = lane >> 2, c2 = (lane & 3) * 2;
    #pragma unroll
    for (int mi = 0; mi < 4; mi++) {
        const int r0 = m0 + wm * 64 + mi * 16 + q;
        #pragma unroll
        for (int nj = 0; nj < 2; nj++) {
            const int col = cb + wn * 16 + nj * 8 + c2;
            if (r0 < cnt) {
                *(__half2*)(C + (size_t)r0 * ldc + col) =
                    __floats2half2_rn(silu_mul(acg[mi][nj][0], acu[mi][nj][0]),
                                      silu_mul(acg[mi][nj][1], acu[mi][nj][1]));
            }
            if (r0 + 8 < cnt) {
                *(__half2*)(C + (size_t)(r0 + 8) * ldc + col) =
                    __floats2half2_rn(silu_mul(acg[mi][nj][2], acu[mi][nj][2]),
                                      silu_mul(acg[mi][nj][3], acu[mi][nj][3]));
            }
        }
    }
}

// ================================================================
// GEMM 2 (fp16 + ldmatrix): out += w * (A Wd^T), via atomicAdd.
// Block 128 M x 128 N.
// ================================================================
__global__ void __launch_bounds__(256, 2) mma_down_kernel(float* __restrict__ out) {
    const int z = blockIdx.z;
    const bool routed = z < E_;
    const int cnt = routed ? g_cnt[z] : T_;
    const int m0  = blockIdx.y * 128;
    if (m0 >= cnt) return;
    const int n0 = blockIdx.x * 128;

    const __half* A;
    const __half* W;
    int lda, ldw;
    if (routed) {
        A = g_inter + (size_t)z * T_ * INTER_; lda = INTER_;
        W = h_dp + (size_t)z * D_ * INTER_;    ldw = INTER_;
    } else {
        const int h = z - E_;
        A = g_hsh + (size_t)h * 512; lda = SH_INTER;
        W = h_sd  + (size_t)h * 512; ldw = SH_INTER;
    }

    extern __shared__ __half smem[];
    __half* As = smem;
    __half* Bs = smem + 2 * PLANE;
    const uint32_t sA = smem_u32(As);
    const uint32_t sB = smem_u32(Bs);

    const int tid = threadIdx.x, wid = tid >> 5, lane = tid & 31;
    const int wm = wid >> 2, wn = wid & 3;

    const __half* agl[2]; const __half* bgl[2];
    uint32_t sa[2], sbo[2];
    #pragma unroll
    for (int t = 0; t < 2; t++) {
        int it = tid + 256 * t;
        int row = it >> 2, c4 = it & 3;
        int mm = m0 + row; if (mm > cnt - 1) mm = cnt - 1;
        agl[t] = A + (size_t)mm * lda + c4 * 8;
        bgl[t] = W + (size_t)(n0 + row) * ldw + c4 * 8;
        sa[t]  = sA + (uint32_t)(row * LDH + c4 * 8) * 2u;
        sbo[t] = sB + (uint32_t)(row * LDH + c4 * 8) * 2u;
    }

    const int alr = lane & 15, alk = (lane >> 4) * 8;
    const uint32_t a_lsm = sA + (uint32_t)(((wm * 64 + alr) * LDH) + alk) * 2u;
    const int bnr = ((lane >> 4) & 1) * 8 + (lane & 7), bkc = ((lane >> 3) & 1) * 8;
    const uint32_t b_lsm = sB + (uint32_t)(((wn * 32 + bnr) * LDH) + bkc) * 2u;

    float acc[4][4][4];
    #pragma unroll
    for (int mi = 0; mi < 4; mi++)
        #pragma unroll
        for (int nj = 0; nj < 4; nj++)
            #pragma unroll
            for (int r = 0; r < 4; r++) acc[mi][nj][r] = 0.f;

    const int NS = INTER_ / 32;   // 16 stages

    #pragma unroll
    for (int t = 0; t < 2; t++) { cp16(sa[t], agl[t]); cp16(sbo[t], bgl[t]); }
    CP_COMMIT();

    for (int s = 0; s < NS; s++) {
        if (s + 1 < NS) {
            const uint32_t bo = (uint32_t)(((s + 1) & 1) * ABYTES);
            #pragma unroll
            for (int t = 0; t < 2; t++) {
                cp16(sa[t] + bo, agl[t] + (s + 1) * 32);
                cp16(sbo[t] + bo, bgl[t] + (s + 1) * 32);
            }
            CP_COMMIT();
            CP_WAIT(1);
        } else {
            CP_WAIT(0);
        }
        __syncthreads();

        const uint32_t po = (uint32_t)((s & 1) * ABYTES);
        #pragma unroll
        for (int ks = 0; ks < 2; ks++) {
            const uint32_t ko = (uint32_t)(ks * 32);
            uint32_t af[4][4];
            #pragma unroll
            for (int mi = 0; mi < 4; mi++)
                ldsm4(af[mi][0], af[mi][1], af[mi][2], af[mi][3],
                      a_lsm + po + ko + (uint32_t)(mi * 16 * LDH * 2));
            uint32_t b[4][2];
            ldsm4(b[0][0], b[0][1], b[1][0], b[1][1], b_lsm + po + ko);
            ldsm4(b[2][0], b[2][1], b[3][0], b[3][1], b_lsm + po + ko + (uint32_t)(16 * LDH * 2));
            #pragma unroll
            for (int nj = 0; nj < 4; nj++)
                #pragma unroll
                for (int mi = 0; mi < 4; mi++)
                    mma_f16(acc[mi][nj], af[mi][0], af[mi][1], af[mi][2], af[mi][3],
                            b[nj][0], b[nj][1]);
        }
        __syncthreads();
    }

    const int q = lane >> 2, c2 = (lane & 3) * 2;
    #pragma unroll
    for (int mi = 0; mi < 4; mi++) {
        #pragma unroll
        for (int half_ = 0; half_ < 2; half_++) {
            const int m = m0 + wm * 64 + mi * 16 + q + half_ * 8;
            if (m >= cnt) continue;
            const int   tok = routed ? g_tok[z * T_ + m] : m;
            const float wt  = routed ? g_wt [z * T_ + m] : 1.f;
            float* op = out + (size_t)tok * D_;
            #pragma unroll
            for (int nj = 0; nj < 4; nj++) {
                const int col = n0 + wn * 32 + nj * 8 + c2;
                atomicAdd(op + col,     wt * acc[mi][nj][half_ * 2 + 0]);
                atomicAdd(op + col + 1, wt * acc[mi][nj][half_ * 2 + 1]);
            }
        }
    }
}

// ---------------- launch ----------------
extern "C" void kernel_launch(void* const* d_in, const int* in_sizes, int n_in,
                              void* d_out, int out_size) {
    const float* x  = (const float*)d_in[0];
    const float* gw = (const float*)d_in[2];
    const float* gb = (const float*)d_in[3];
    const float* gp = (const float*)d_in[4];
    const float* up = (const float*)d_in[5];
    const float* dp = (const float*)d_in[6];
    const float* sg = (const float*)d_in[7];
    const float* su = (const float*)d_in[8];
    const float* sd = (const float*)d_in[9];
    float* out = (float*)d_out;

    cudaFuncSetAttribute(mma_gu_kernel,   cudaFuncAttributeMaxDynamicSharedMemorySize, SMEM_BYTES);
    cudaFuncSetAttribute(mma_down_kernel, cudaFuncAttributeMaxDynamicSharedMemorySize, SMEM_BYTES);

    __half *p_x, *p_gp, *p_up, *p_dp, *p_sg, *p_su, *p_sd;
    cudaGetSymbolAddress((void**)&p_x,  h_x);
    cudaGetSymbolAddress((void**)&p_gp, h_gp);
    cudaGetSymbolAddress((void**)&p_up, h_up);
    cudaGetSymbolAddress((void**)&p_dp, h_dp);
    cudaGetSymbolAddress((void**)&p_sg, h_sg);
    cudaGetSymbolAddress((void**)&p_su, h_su);
    cudaGetSymbolAddress((void**)&p_sd, h_sd);

    cudaMemsetAsync(out, 0, (size_t)T_ * D_ * sizeof(float), 0);
    zero_counts_kernel<<<1, 32>>>();

    const int NB = 256;
    const int big8 = E_ * INTER_ * D_ / 8;   // 1M chunks of 8 floats
    cvt3_kernel<<<(3 * big8 + NB - 1) / NB, NB>>>(p_gp, gp, p_up, up, p_dp, dp, big8);
    cvt_kernel<<<(T_ * D_ / 8 + NB - 1) / NB, NB>>>(p_x, x, T_ * D_ / 8);
    cvt_kernel<<<(SH_INTER * D_ / 8 + NB - 1) / NB, NB>>>(p_sg, sg, SH_INTER * D_ / 8);
    cvt_kernel<<<(SH_INTER * D_ / 8 + NB - 1) / NB, NB>>>(p_su, su, SH_INTER * D_ / 8);
    cvt_kernel<<<(D_ * SH_INTER / 8 + NB - 1) / NB, NB>>>(p_sd, sd, D_ * SH_INTER / 8);

    route_kernel<<<T_, 128>>>(x, gw, gb);

    mma_gu_kernel<<<dim3(8, T_ / 128, NZ), 256, SMEM_BYTES>>>();
    mma_down_kernel<<<dim3(D_ / 128, T_ / 128, NZ), 256, SMEM_BYTES>>>(out);
}

// round 9
// speedup vs baseline: 1.4284x; 1.0592x over previous
#include <cuda_runtime.h>
#include <cuda_fp16.h>
#include <math.h>
#include <stdint.h>

// Problem constants
#define T_       1024
#define D_       1024
#define E_       16
#define K_SEL    4
#define NGRP     4
#define INTER_   512
#define SH_INTER 1024
#define RSCALE   2.5f

#define LDH   40                      // smem row stride in halves (80B, LDSM conflict-free)
#define PLANE (128 * LDH)             // halves per plane-stage
#define ABYTES (PLANE * 2)            // 10240 B
#define NSTG  3
#define SMEM_BYTES (2 * NSTG * ABYTES)   // A0..2,B0..2 = 61440 B
#define NZ    18                      // 16 routed experts + 2 shared halves

// ---------------- device scratch (fp16 operands) ----------------
__device__ int    g_cnt[E_];
__device__ int    g_tok[E_ * T_];
__device__ float  g_wt [E_ * T_];
__device__ __half h_x [(size_t)T_ * D_];
__device__ __half h_gp[(size_t)E_ * INTER_ * D_];
__device__ __half h_up[(size_t)E_ * INTER_ * D_];
__device__ __half h_dp[(size_t)E_ * D_ * INTER_];
__device__ __half h_sg[(size_t)SH_INTER * D_];
__device__ __half h_su[(size_t)SH_INTER * D_];
__device__ __half h_sd[(size_t)D_ * SH_INTER];
__device__ __half g_inter[(size_t)E_ * T_ * INTER_];
__device__ __half g_hsh[(size_t)T_ * SH_INTER];

// ---------------- helpers ----------------
__device__ __forceinline__ uint32_t smem_u32(const void* p) {
    uint32_t a;
    asm("{ .reg .u64 t; cvta.to.shared.u64 t, %1; cvt.u32.u64 %0, t; }" : "=r"(a) : "l"(p));
    return a;
}
__device__ __forceinline__ void cp16(uint32_t s, const void* g) {
    asm volatile("cp.async.cg.shared.global [%0], [%1], 16;" :: "r"(s), "l"(g) : "memory");
}
#define CP_COMMIT() asm volatile("cp.async.commit_group;" ::: "memory")
#define CP_WAIT(n)  asm volatile("cp.async.wait_group %0;" :: "n"(n) : "memory")

__device__ __forceinline__ void ldsm4(uint32_t& r0, uint32_t& r1, uint32_t& r2, uint32_t& r3,
                                      uint32_t addr) {
    asm volatile("ldmatrix.sync.aligned.m8n8.x4.shared.b16 {%0,%1,%2,%3}, [%4];"
                 : "=r"(r0), "=r"(r1), "=r"(r2), "=r"(r3) : "r"(addr));
}
__device__ __forceinline__ void mma_f16(float c[4],
                                        uint32_t a0, uint32_t a1, uint32_t a2, uint32_t a3,
                                        uint32_t b0, uint32_t b1) {
    asm volatile(
        "mma.sync.aligned.m16n8k16.row.col.f32.f16.f16.f32 "
        "{%0,%1,%2,%3}, {%4,%5,%6,%7}, {%8,%9}, {%0,%1,%2,%3};"
        : "+f"(c[0]), "+f"(c[1]), "+f"(c[2]), "+f"(c[3])
        : "r"(a0), "r"(a1), "r"(a2), "r"(a3), "r"(b0), "r"(b1));
}
__device__ __forceinline__ float silu_mul(float g, float u) {
    return g / (1.f + expf(-g)) * u;
}

// ---------------- fused fp32 -> fp16 conversion (all 7 tensors) ----------------
#define BIG8   (E_ * INTER_ * D_ / 8)        // 1048576 chunks per big tensor
#define SML8   (SH_INTER * D_ / 8)           // 131072 per small tensor
#define TOT8   (3 * BIG8 + 4 * SML8)

__global__ void cvt_all_kernel(const float* __restrict__ gp, const float* __restrict__ up,
                               const float* __restrict__ dp, const float* __restrict__ x,
                               const float* __restrict__ sg, const float* __restrict__ su,
                               const float* __restrict__ sd) {
    int i = blockIdx.x * blockDim.x + threadIdx.x;
    if (i >= TOT8) return;
    const float* s; __half* d;
    if (i < BIG8)                 { s = gp; d = h_gp; }
    else if (i < 2 * BIG8)        { s = up; d = h_up; i -= BIG8; }
    else if (i < 3 * BIG8)        { s = dp; d = h_dp; i -= 2 * BIG8; }
    else {
        i -= 3 * BIG8;
        if (i < SML8)             { s = x;  d = h_x; }
        else if (i < 2 * SML8)    { s = sg; d = h_sg; i -= SML8; }
        else if (i < 3 * SML8)    { s = su; d = h_su; i -= 2 * SML8; }
        else                      { s = sd; d = h_sd; i -= 3 * SML8; }
    }
    float4 v0 = ((const float4*)s)[2 * i];
    float4 v1 = ((const float4*)s)[2 * i + 1];
    ((__half2*)d)[4 * i + 0] = __floats2half2_rn(v0.x, v0.y);
    ((__half2*)d)[4 * i + 1] = __floats2half2_rn(v0.z, v0.w);
    ((__half2*)d)[4 * i + 2] = __floats2half2_rn(v1.x, v1.y);
    ((__half2*)d)[4 * i + 3] = __floats2half2_rn(v1.z, v1.w);
}

// ---------------- routing ----------------
__global__ void zero_counts_kernel() {
    if (threadIdx.x < E_) g_cnt[threadIdx.x] = 0;
}

__global__ void route_kernel(const float* __restrict__ x,
                             const float* __restrict__ gw,
                             const float* __restrict__ gb) {
    const int t = blockIdx.x;
    __shared__ float xs[D_];
    __shared__ float sc[E_];
    const int tid = threadIdx.x;  // 128
    const float4* xr = (const float4*)(x + (size_t)t * D_);
    float4* xs4 = (float4*)xs;
    for (int i = tid; i < D_ / 4; i += 128) xs4[i] = xr[i];
    __syncthreads();

    const int warp = tid >> 5, lane = tid & 31;
    for (int e = warp * 4; e < warp * 4 + 4; e++) {
        const float* w = gw + (size_t)e * D_;
        float p = 0.f;
        for (int j = lane; j < D_; j += 32) p += xs[j] * w[j];
        #pragma unroll
        for (int o = 16; o; o >>= 1) p += __shfl_xor_sync(0xffffffffu, p, o);
        if (lane == 0) sc[e] = 1.f / (1.f + expf(-p));
    }
    __syncthreads();

    if (tid == 0) {
        float s[E_];
        #pragma unroll
        for (int e = 0; e < E_; e++) s[e] = sc[e] + gb[e];
        float gsc[NGRP];
        #pragma unroll
        for (int g = 0; g < NGRP; g++) {
            float m1 = -1e30f, m2 = -1e30f;
            #pragma unroll
            for (int j = 0; j < 4; j++) {
                float v = s[g * 4 + j];
                if (v > m1) { m2 = m1; m1 = v; } else if (v > m2) { m2 = v; }
            }
            gsc[g] = m1 + m2;
        }
        int g1 = 0;
        for (int g = 1; g < NGRP; g++) if (gsc[g] > gsc[g1]) g1 = g;
        int g2 = -1;
        for (int g = 0; g < NGRP; g++) {
            if (g == g1) continue;
            if (g2 < 0 || gsc[g] > gsc[g2]) g2 = g;
        }
        float masked[E_];
        #pragma unroll
        for (int e = 0; e < E_; e++) {
            int g = e >> 2;
            masked[e] = (g == g1 || g == g2) ? s[e] : 0.f;
        }
        int idx[K_SEL];
        float w[K_SEL];
        bool used[E_];
        #pragma unroll
        for (int e = 0; e < E_; e++) used[e] = false;
        float wsum = 0.f;
        for (int k = 0; k < K_SEL; k++) {
            int best = -1; float bv = -1e30f;
            for (int e = 0; e < E_; e++) {
                if (used[e]) continue;
                if (masked[e] > bv) { bv = masked[e]; best = e; }
            }
            used[best] = true;
            idx[k] = best;
            w[k] = sc[best];
            wsum += w[k];
        }
        const float scale = RSCALE / wsum;
        for (int k = 0; k < K_SEL; k++) {
            int e = idx[k];
            int pos = atomicAdd(&g_cnt[e], 1);
            g_tok[e * T_ + pos] = t;
            g_wt [e * T_ + pos] = w[k] * scale;
        }
    }
}

// ================================================================
// GEMM 1 (fp16 + ldmatrix + 3-stage single-barrier pipeline)
// ================================================================
__global__ void __launch_bounds__(256, 2) mma_gu_kernel() {
    const int z = blockIdx.z;
    const bool routed = z < E_;
    const int cnt = routed ? g_cnt[z] : T_;
    const int m0  = blockIdx.y * 128;
    if (m0 >= cnt) return;
    const int n0 = blockIdx.x * 64;

    const __half* Wg;
    const __half* Wu;
    __half* C;
    int ldc, cb;
    if (routed) {
        Wg = h_gp + ((size_t)z * INTER_ + n0) * D_;
        Wu = h_up + ((size_t)z * INTER_ + n0) * D_;
        C = g_inter + (size_t)z * T_ * INTER_;
        ldc = INTER_; cb = n0;
    } else {
        const int h = z - E_;
        Wg = h_sg + ((size_t)h * 512 + n0) * D_;
        Wu = h_su + ((size_t)h * 512 + n0) * D_;
        C = g_hsh;
        ldc = SH_INTER; cb = h * 512 + n0;
    }

    extern __shared__ __half smem[];
    __half* As = smem;                    // [NSTG][128][LDH]
    __half* Bs = smem + NSTG * PLANE;     // [NSTG][128][LDH]
    const uint32_t sA = smem_u32(As);
    const uint32_t sB = smem_u32(Bs);

    const int tid = threadIdx.x, wid = tid >> 5, lane = tid & 31;
    const int wm = wid >> 2, wn = wid & 3;

    const __half* agl[2]; const __half* bgl[2];
    uint32_t sa[2], sbo[2];
    #pragma unroll
    for (int t = 0; t < 2; t++) {
        int it = tid + 256 * t;
        int row = it >> 2, c4 = it & 3;
        int mm = m0 + row; if (mm > cnt - 1) mm = cnt - 1;
        int ar = routed ? g_tok[z * T_ + mm] : mm;
        agl[t] = h_x + (size_t)ar * D_ + c4 * 8;
        bgl[t] = ((row < 64) ? (Wg + (size_t)row * D_) : (Wu + (size_t)(row - 64) * D_)) + c4 * 8;
        sa[t]  = sA + (uint32_t)(row * LDH + c4 * 8) * 2u;
        sbo[t] = sB + (uint32_t)(row * LDH + c4 * 8) * 2u;
    }

    const int alr = lane & 15, alk = (lane >> 4) * 8;
    const uint32_t a_lsm = sA + (uint32_t)(((wm * 64 + alr) * LDH) + alk) * 2u;
    const int bnr = ((lane >> 4) & 1) * 8 + (lane & 7), bkc = ((lane >> 3) & 1) * 8;
    const uint32_t bg_lsm = sB + (uint32_t)(((wn * 16 + bnr) * LDH) + bkc) * 2u;
    const uint32_t bu_lsm = sB + (uint32_t)(((wn * 16 + bnr + 64) * LDH) + bkc) * 2u;

    float acg[4][2][4], acu[4][2][4];
    #pragma unroll
    for (int mi = 0; mi < 4; mi++)
        #pragma unroll
        for (int nj = 0; nj < 2; nj++)
            #pragma unroll
            for (int r = 0; r < 4; r++) { acg[mi][nj][r] = 0.f; acu[mi][nj][r] = 0.f; }

    const int NS = D_ / 32;   // 32 stages

    // prologue: stages 0,1
    #pragma unroll
    for (int p = 0; p < 2; p++) {
        const uint32_t bo = (uint32_t)(p * ABYTES);
        #pragma unroll
        for (int t = 0; t < 2; t++) { cp16(sa[t] + bo, agl[t] + p * 32); cp16(sbo[t] + bo, bgl[t] + p * 32); }
        CP_COMMIT();
    }

    int buf = 0, pbuf = 2;
    for (int s = 0; s < NS; s++) {
        if (s + 1 < NS) CP_WAIT(1); else CP_WAIT(0);
        __syncthreads();
        if (s + 2 < NS) {
            const uint32_t bo = (uint32_t)(pbuf * ABYTES);
            #pragma unroll
            for (int t = 0; t < 2; t++) {
                cp16(sa[t] + bo, agl[t] + (s + 2) * 32);
                cp16(sbo[t] + bo, bgl[t] + (s + 2) * 32);
            }
            CP_COMMIT();
        }

        const uint32_t po = (uint32_t)(buf * ABYTES);
        #pragma unroll
        for (int ks = 0; ks < 2; ks++) {
            const uint32_t ko = (uint32_t)(ks * 32);   // 16 halves
            uint32_t af[4][4];
            #pragma unroll
            for (int mi = 0; mi < 4; mi++)
                ldsm4(af[mi][0], af[mi][1], af[mi][2], af[mi][3],
                      a_lsm + po + ko + (uint32_t)(mi * 16 * LDH * 2));
            uint32_t bg0a, bg1a, bg0b, bg1b, bu0a, bu1a, bu0b, bu1b;
            ldsm4(bg0a, bg1a, bg0b, bg1b, bg_lsm + po + ko);
            ldsm4(bu0a, bu1a, bu0b, bu1b, bu_lsm + po + ko);
            #pragma unroll
            for (int mi = 0; mi < 4; mi++) {
                mma_f16(acg[mi][0], af[mi][0], af[mi][1], af[mi][2], af[mi][3], bg0a, bg1a);
                mma_f16(acg[mi][1], af[mi][0], af[mi][1], af[mi][2], af[mi][3], bg0b, bg1b);
                mma_f16(acu[mi][0], af[mi][0], af[mi][1], af[mi][2], af[mi][3], bu0a, bu1a);
                mma_f16(acu[mi][1], af[mi][0], af[mi][1], af[mi][2], af[mi][3], bu0b, bu1b);
            }
        }
        buf = (buf == NSTG - 1) ? 0 : buf + 1;
        pbuf = (pbuf == NSTG - 1) ? 0 : pbuf + 1;
    }

    // epilogue: SwiGLU -> fp16 C
    const int q = lane >> 2, c2 = (lane & 3) * 2;
    #pragma unroll
    for (int mi = 0; mi < 4; mi++) {
        const int r0 = m0 + wm * 64 + mi * 16 + q;
        #pragma unroll
        for (int nj = 0; nj < 2; nj++) {
            const int col = cb + wn * 16 + nj * 8 + c2;
            if (r0 < cnt) {
                *(__half2*)(C + (size_t)r0 * ldc + col) =
                    __floats2half2_rn(silu_mul(acg[mi][nj][0], acu[mi][nj][0]),
                                      silu_mul(acg[mi][nj][1], acu[mi][nj][1]));
            }
            if (r0 + 8 < cnt) {
                *(__half2*)(C + (size_t)(r0 + 8) * ldc + col) =
                    __floats2half2_rn(silu_mul(acg[mi][nj][2], acu[mi][nj][2]),
                                      silu_mul(acg[mi][nj][3], acu[mi][nj][3]));
            }
        }
    }
}

// ================================================================
// GEMM 2 (fp16 + ldmatrix + 3-stage single-barrier pipeline)
// ================================================================
__global__ void __launch_bounds__(256, 2) mma_down_kernel(float* __restrict__ out) {
    const int z = blockIdx.z;
    const bool routed = z < E_;
    const int cnt = routed ? g_cnt[z] : T_;
    const int m0  = blockIdx.y * 128;
    if (m0 >= cnt) return;
    const int n0 = blockIdx.x * 128;

    const __half* A;
    const __half* W;
    int lda, ldw;
    if (routed) {
        A = g_inter + (size_t)z * T_ * INTER_; lda = INTER_;
        W = h_dp + (size_t)z * D_ * INTER_;    ldw = INTER_;
    } else {
        const int h = z - E_;
        A = g_hsh + (size_t)h * 512; lda = SH_INTER;
        W = h_sd  + (size_t)h * 512; ldw = SH_INTER;
    }

    extern __shared__ __half smem[];
    __half* As = smem;
    __half* Bs = smem + NSTG * PLANE;
    const uint32_t sA = smem_u32(As);
    const uint32_t sB = smem_u32(Bs);

    const int tid = threadIdx.x, wid = tid >> 5, lane = tid & 31;
    const int wm = wid >> 2, wn = wid & 3;

    const __half* agl[2]; const __half* bgl[2];
    uint32_t sa[2], sbo[2];
    #pragma unroll
    for (int t = 0; t < 2; t++) {
        int it = tid + 256 * t;
        int row = it >> 2, c4 = it & 3;
        int mm = m0 + row; if (mm > cnt - 1) mm = cnt - 1;
        agl[t] = A + (size_t)mm * lda + c4 * 8;
        bgl[t] = W + (size_t)(n0 + row) * ldw + c4 * 8;
        sa[t]  = sA + (uint32_t)(row * LDH + c4 * 8) * 2u;
        sbo[t] = sB + (uint32_t)(row * LDH + c4 * 8) * 2u;
    }

    const int alr = lane & 15, alk = (lane >> 4) * 8;
    const uint32_t a_lsm = sA + (uint32_t)(((wm * 64 + alr) * LDH) + alk) * 2u;
    const int bnr = ((lane >> 4) & 1) * 8 + (lane & 7), bkc = ((lane >> 3) & 1) * 8;
    const uint32_t b_lsm = sB + (uint32_t)(((wn * 32 + bnr) * LDH) + bkc) * 2u;

    float acc[4][4][4];
    #pragma unroll
    for (int mi = 0; mi < 4; mi++)
        #pragma unroll
        for (int nj = 0; nj < 4; nj++)
            #pragma unroll
            for (int r = 0; r < 4; r++) acc[mi][nj][r] = 0.f;

    const int NS = INTER_ / 32;   // 16 stages

    #pragma unroll
    for (int p = 0; p < 2; p++) {
        const uint32_t bo = (uint32_t)(p * ABYTES);
        #pragma unroll
        for (int t = 0; t < 2; t++) { cp16(sa[t] + bo, agl[t] + p * 32); cp16(sbo[t] + bo, bgl[t] + p * 32); }
        CP_COMMIT();
    }

    int buf = 0, pbuf = 2;
    for (int s = 0; s < NS; s++) {
        if (s + 1 < NS) CP_WAIT(1); else CP_WAIT(0);
        __syncthreads();
        if (s + 2 < NS) {
            const uint32_t bo = (uint32_t)(pbuf * ABYTES);
            #pragma unroll
            for (int t = 0; t < 2; t++) {
                cp16(sa[t] + bo, agl[t] + (s + 2) * 32);
                cp16(sbo[t] + bo, bgl[t] + (s + 2) * 32);
            }
            CP_COMMIT();
        }

        const uint32_t po = (uint32_t)(buf * ABYTES);
        #pragma unroll
        for (int ks = 0; ks < 2; ks++) {
            const uint32_t ko = (uint32_t)(ks * 32);
            uint32_t af[4][4];
            #pragma unroll
            for (int mi = 0; mi < 4; mi++)
                ldsm4(af[mi][0], af[mi][1], af[mi][2], af[mi][3],
                      a_lsm + po + ko + (uint32_t)(mi * 16 * LDH * 2));
            uint32_t b[4][2];
            ldsm4(b[0][0], b[0][1], b[1][0], b[1][1], b_lsm + po + ko);
            ldsm4(b[2][0], b[2][1], b[3][0], b[3][1], b_lsm + po + ko + (uint32_t)(16 * LDH * 2));
            #pragma unroll
            for (int nj = 0; nj < 4; nj++)
                #pragma unroll
                for (int mi = 0; mi < 4; mi++)
                    mma_f16(acc[mi][nj], af[mi][0], af[mi][1], af[mi][2], af[mi][3],
                            b[nj][0], b[nj][1]);
        }
        buf = (buf == NSTG - 1) ? 0 : buf + 1;
        pbuf = (pbuf == NSTG - 1) ? 0 : pbuf + 1;
    }

    const int q = lane >> 2, c2 = (lane & 3) * 2;
    #pragma unroll
    for (int mi = 0; mi < 4; mi++) {
        #pragma unroll
        for (int half_ = 0; half_ < 2; half_++) {
            const int m = m0 + wm * 64 + mi * 16 + q + half_ * 8;
            if (m >= cnt) continue;
            const int   tok = routed ? g_tok[z * T_ + m] : m;
            const float wt  = routed ? g_wt [z * T_ + m] : 1.f;
            float* op = out + (size_t)tok * D_;
            #pragma unroll
            for (int nj = 0; nj < 4; nj++) {
                const int col = n0 + wn * 32 + nj * 8 + c2;
                atomicAdd(op + col,     wt * acc[mi][nj][half_ * 2 + 0]);
                atomicAdd(op + col + 1, wt * acc[mi][nj][half_ * 2 + 1]);
            }
        }
    }
}

// ---------------- launch ----------------
extern "C" void kernel_launch(void* const* d_in, const int* in_sizes, int n_in,
                              void* d_out, int out_size) {
    const float* x  = (const float*)d_in[0];
    const float* gw = (const float*)d_in[2];
    const float* gb = (const float*)d_in[3];
    const float* gp = (const float*)d_in[4];
    const float* up = (const float*)d_in[5];
    const float* dp = (const float*)d_in[6];
    const float* sg = (const float*)d_in[7];
    const float* su = (const float*)d_in[8];
    const float* sd = (const float*)d_in[9];
    float* out = (float*)d_out;

    cudaFuncSetAttribute(mma_gu_kernel,   cudaFuncAttributeMaxDynamicSharedMemorySize, SMEM_BYTES);
    cudaFuncSetAttribute(mma_down_kernel, cudaFuncAttributeMaxDynamicSharedMemorySize, SMEM_BYTES);

    cudaMemsetAsync(out, 0, (size_t)T_ * D_ * sizeof(float), 0);
    zero_counts_kernel<<<1, 32>>>();

    const int NB = 256;
    cvt_all_kernel<<<(TOT8 + NB - 1) / NB, NB>>>(gp, up, dp, x, sg, su, sd);
    route_kernel<<<T_, 128>>>(x, gw, gb);

    mma_gu_kernel<<<dim3(8, T_ / 128, NZ), 256, SMEM_BYTES>>>();
    mma_down_kernel<<<dim3(D_ / 128, T_ / 128, NZ), 256, SMEM_BYTES>>>(out);
}

// round 10
// speedup vs baseline: 1.4545x; 1.0182x over previous
#include <cuda_runtime.h>
#include <cuda_fp16.h>
#include <math.h>
#include <stdint.h>

// Problem constants
#define T_       1024
#define D_       1024
#define E_       16
#define K_SEL    4
#define NGRP     4
#define INTER_   512
#define SH_INTER 1024
#define RSCALE   2.5f

#define LDH   40                      // smem row stride in halves (80B, LDSM conflict-free)
#define PLANE (128 * LDH)             // halves per plane-stage
#define ABYTES (PLANE * 2)            // 10240 B
#define NSTG  3
#define SMEM_BYTES (2 * NSTG * ABYTES)   // 61440 B
#define NZ    18                      // 16 routed experts + 2 shared halves

// ---------------- device scratch (fp16 operands) ----------------
__device__ int    g_cnt[E_];
__device__ int    g_tok[E_ * T_];
__device__ float  g_wt [E_ * T_];
__device__ __half h_x [(size_t)T_ * D_];
__device__ __half h_gp[(size_t)E_ * INTER_ * D_];
__device__ __half h_up[(size_t)E_ * INTER_ * D_];
__device__ __half h_dp[(size_t)E_ * D_ * INTER_];
__device__ __half h_sg[(size_t)SH_INTER * D_];
__device__ __half h_su[(size_t)SH_INTER * D_];
__device__ __half h_sd[(size_t)D_ * SH_INTER];
__device__ __half g_inter[(size_t)E_ * T_ * INTER_];
__device__ __half g_hsh[(size_t)T_ * SH_INTER];

// ---------------- helpers ----------------
__device__ __forceinline__ uint32_t smem_u32(const void* p) {
    uint32_t a;
    asm("{ .reg .u64 t; cvta.to.shared.u64 t, %1; cvt.u32.u64 %0, t; }" : "=r"(a) : "l"(p));
    return a;
}
__device__ __forceinline__ void cp16(uint32_t s, const void* g) {
    asm volatile("cp.async.cg.shared.global [%0], [%1], 16;" :: "r"(s), "l"(g) : "memory");
}
#define CP_COMMIT() asm volatile("cp.async.commit_group;" ::: "memory")
#define CP_WAIT(n)  asm volatile("cp.async.wait_group %0;" :: "n"(n) : "memory")

__device__ __forceinline__ void ldsm4(uint32_t& r0, uint32_t& r1, uint32_t& r2, uint32_t& r3,
                                      uint32_t addr) {
    asm volatile("ldmatrix.sync.aligned.m8n8.x4.shared.b16 {%0,%1,%2,%3}, [%4];"
                 : "=r"(r0), "=r"(r1), "=r"(r2), "=r"(r3) : "r"(addr));
}
__device__ __forceinline__ void mma_f16(float c[4],
                                        uint32_t a0, uint32_t a1, uint32_t a2, uint32_t a3,
                                        uint32_t b0, uint32_t b1) {
    asm volatile(
        "mma.sync.aligned.m16n8k16.row.col.f32.f16.f16.f32 "
        "{%0,%1,%2,%3}, {%4,%5,%6,%7}, {%8,%9}, {%0,%1,%2,%3};"
        : "+f"(c[0]), "+f"(c[1]), "+f"(c[2]), "+f"(c[3])
        : "r"(a0), "r"(a1), "r"(a2), "r"(a3), "r"(b0), "r"(b1));
}
__device__ __forceinline__ float silu_mul(float g, float u) {
    return g / (1.f + expf(-g)) * u;
}

// ---------------- fused fp32 -> fp16 conversion ----------------
#define BIG8   (E_ * INTER_ * D_ / 8)
#define SML8   (SH_INTER * D_ / 8)

__device__ __forceinline__ void cvt_chunk(const float* s, __half* d, int i) {
    float4 v0 = ((const float4*)s)[2 * i];
    float4 v1 = ((const float4*)s)[2 * i + 1];
    ((__half2*)d)[4 * i + 0] = __floats2half2_rn(v0.x, v0.y);
    ((__half2*)d)[4 * i + 1] = __floats2half2_rn(v0.z, v0.w);
    ((__half2*)d)[4 * i + 2] = __floats2half2_rn(v1.x, v1.y);
    ((__half2*)d)[4 * i + 3] = __floats2half2_rn(v1.z, v1.w);
}

// gu-side: gp, up, x, sg, su
#define GUW8 (2 * BIG8 + 3 * SML8)
__global__ void cvt_guw_kernel(const float* __restrict__ gp, const float* __restrict__ up,
                               const float* __restrict__ x,  const float* __restrict__ sg,
                               const float* __restrict__ su) {
    int i = blockIdx.x * blockDim.x + threadIdx.x;
    if (i >= GUW8) return;
    const float* s; __half* d;
    if (i < BIG8)              { s = gp; d = h_gp; }
    else if (i < 2 * BIG8)     { s = up; d = h_up; i -= BIG8; }
    else {
        i -= 2 * BIG8;
        if (i < SML8)          { s = x;  d = h_x; }
        else if (i < 2 * SML8) { s = sg; d = h_sg; i -= SML8; }
        else                   { s = su; d = h_su; i -= 2 * SML8; }
    }
    cvt_chunk(s, d, i);
}

// down-side: dp, sd
#define DW8 (BIG8 + SML8)
__global__ void cvt_dw_kernel(const float* __restrict__ dp, const float* __restrict__ sd) {
    int i = blockIdx.x * blockDim.x + threadIdx.x;
    if (i >= DW8) return;
    if (i < BIG8) cvt_chunk(dp, h_dp, i);
    else          cvt_chunk(sd, h_sd, i - BIG8);
}

// ---------------- routing ----------------
__global__ void zero_counts_kernel() {
    if (threadIdx.x < E_) g_cnt[threadIdx.x] = 0;
}

__global__ void route_kernel(const float* __restrict__ x,
                             const float* __restrict__ gw,
                             const float* __restrict__ gb) {
    const int t = blockIdx.x;
    __shared__ float xs[D_];
    __shared__ float sc[E_];
    const int tid = threadIdx.x;  // 128
    const float4* xr = (const float4*)(x + (size_t)t * D_);
    float4* xs4 = (float4*)xs;
    for (int i = tid; i < D_ / 4; i += 128) xs4[i] = xr[i];
    __syncthreads();

    const int warp = tid >> 5, lane = tid & 31;
    for (int e = warp * 4; e < warp * 4 + 4; e++) {
        const float* w = gw + (size_t)e * D_;
        float p = 0.f;
        for (int j = lane; j < D_; j += 32) p += xs[j] * w[j];
        #pragma unroll
        for (int o = 16; o; o >>= 1) p += __shfl_xor_sync(0xffffffffu, p, o);
        if (lane == 0) sc[e] = 1.f / (1.f + expf(-p));
    }
    __syncthreads();

    if (tid == 0) {
        float s[E_];
        #pragma unroll
        for (int e = 0; e < E_; e++) s[e] = sc[e] + gb[e];
        float gsc[NGRP];
        #pragma unroll
        for (int g = 0; g < NGRP; g++) {
            float m1 = -1e30f, m2 = -1e30f;
            #pragma unroll
            for (int j = 0; j < 4; j++) {
                float v = s[g * 4 + j];
                if (v > m1) { m2 = m1; m1 = v; } else if (v > m2) { m2 = v; }
            }
            gsc[g] = m1 + m2;
        }
        int g1 = 0;
        for (int g = 1; g < NGRP; g++) if (gsc[g] > gsc[g1]) g1 = g;
        int g2 = -1;
        for (int g = 0; g < NGRP; g++) {
            if (g == g1) continue;
            if (g2 < 0 || gsc[g] > gsc[g2]) g2 = g;
        }
        float masked[E_];
        #pragma unroll
        for (int e = 0; e < E_; e++) {
            int g = e >> 2;
            masked[e] = (g == g1 || g == g2) ? s[e] : 0.f;
        }
        int idx[K_SEL];
        float w[K_SEL];
        bool used[E_];
        #pragma unroll
        for (int e = 0; e < E_; e++) used[e] = false;
        float wsum = 0.f;
        for (int k = 0; k < K_SEL; k++) {
            int best = -1; float bv = -1e30f;
            for (int e = 0; e < E_; e++) {
                if (used[e]) continue;
                if (masked[e] > bv) { bv = masked[e]; best = e; }
            }
            used[best] = true;
            idx[k] = best;
            w[k] = sc[best];
            wsum += w[k];
        }
        const float scale = RSCALE / wsum;
        for (int k = 0; k < K_SEL; k++) {
            int e = idx[k];
            int pos = atomicAdd(&g_cnt[e], 1);
            g_tok[e * T_ + pos] = t;
            g_wt [e * T_ + pos] = w[k] * scale;
        }
    }
}

// ================================================================
// GEMM 1 (fp16 + ldmatrix + 3-stage single-barrier pipeline)
// ================================================================
__global__ void __launch_bounds__(256, 2) mma_gu_kernel() {
    const int z = blockIdx.z;
    const bool routed = z < E_;
    const int cnt = routed ? g_cnt[z] : T_;
    const int m0  = blockIdx.y * 128;
    if (m0 >= cnt) return;
    const int n0 = blockIdx.x * 64;

    const __half* Wg;
    const __half* Wu;
    __half* C;
    int ldc, cb;
    if (routed) {
        Wg = h_gp + ((size_t)z * INTER_ + n0) * D_;
        Wu = h_up + ((size_t)z * INTER_ + n0) * D_;
        C = g_inter + (size_t)z * T_ * INTER_;
        ldc = INTER_; cb = n0;
    } else {
        const int h = z - E_;
        Wg = h_sg + ((size_t)h * 512 + n0) * D_;
        Wu = h_su + ((size_t)h * 512 + n0) * D_;
        C = g_hsh;
        ldc = SH_INTER; cb = h * 512 + n0;
    }

    extern __shared__ __half smem[];
    __half* As = smem;
    __half* Bs = smem + NSTG * PLANE;
    const uint32_t sA = smem_u32(As);
    const uint32_t sB = smem_u32(Bs);

    const int tid = threadIdx.x, wid = tid >> 5, lane = tid & 31;
    const int wm = wid >> 2, wn = wid & 3;

    const __half* agl[2]; const __half* bgl[2];
    uint32_t sa[2], sbo[2];
    #pragma unroll
    for (int t = 0; t < 2; t++) {
        int it = tid + 256 * t;
        int row = it >> 2, c4 = it & 3;
        int mm = m0 + row; if (mm > cnt - 1) mm = cnt - 1;
        int ar = routed ? g_tok[z * T_ + mm] : mm;
        agl[t] = h_x + (size_t)ar * D_ + c4 * 8;
        bgl[t] = ((row < 64) ? (Wg + (size_t)row * D_) : (Wu + (size_t)(row - 64) * D_)) + c4 * 8;
        sa[t]  = sA + (uint32_t)(row * LDH + c4 * 8) * 2u;
        sbo[t] = sB + (uint32_t)(row * LDH + c4 * 8) * 2u;
    }

    const int alr = lane & 15, alk = (lane >> 4) * 8;
    const uint32_t a_lsm = sA + (uint32_t)(((wm * 64 + alr) * LDH) + alk) * 2u;
    const int bnr = ((lane >> 4) & 1) * 8 + (lane & 7), bkc = ((lane >> 3) & 1) * 8;
    const uint32_t bg_lsm = sB + (uint32_t)(((wn * 16 + bnr) * LDH) + bkc) * 2u;
    const uint32_t bu_lsm = sB + (uint32_t)(((wn * 16 + bnr + 64) * LDH) + bkc) * 2u;

    float acg[4][2][4], acu[4][2][4];
    #pragma unroll
    for (int mi = 0; mi < 4; mi++)
        #pragma unroll
        for (int nj = 0; nj < 2; nj++)
            #pragma unroll
            for (int r = 0; r < 4; r++) { acg[mi][nj][r] = 0.f; acu[mi][nj][r] = 0.f; }

    const int NS = D_ / 32;   // 32 stages

    #pragma unroll
    for (int p = 0; p < 2; p++) {
        const uint32_t bo = (uint32_t)(p * ABYTES);
        #pragma unroll
        for (int t = 0; t < 2; t++) { cp16(sa[t] + bo, agl[t] + p * 32); cp16(sbo[t] + bo, bgl[t] + p * 32); }
        CP_COMMIT();
    }

    int buf = 0, pbuf = 2;
    for (int s = 0; s < NS; s++) {
        if (s + 1 < NS) CP_WAIT(1); else CP_WAIT(0);
        __syncthreads();
        if (s + 2 < NS) {
            const uint32_t bo = (uint32_t)(pbuf * ABYTES);
            #pragma unroll
            for (int t = 0; t < 2; t++) {
                cp16(sa[t] + bo, agl[t] + (s + 2) * 32);
                cp16(sbo[t] + bo, bgl[t] + (s + 2) * 32);
            }
            CP_COMMIT();
        }

        const uint32_t po = (uint32_t)(buf * ABYTES);
        #pragma unroll
        for (int ks = 0; ks < 2; ks++) {
            const uint32_t ko = (uint32_t)(ks * 32);
            uint32_t af[4][4];
            #pragma unroll
            for (int mi = 0; mi < 4; mi++)
                ldsm4(af[mi][0], af[mi][1], af[mi][2], af[mi][3],
                      a_lsm + po + ko + (uint32_t)(mi * 16 * LDH * 2));
            uint32_t bg0a, bg1a, bg0b, bg1b, bu0a, bu1a, bu0b, bu1b;
            ldsm4(bg0a, bg1a, bg0b, bg1b, bg_lsm + po + ko);
            ldsm4(bu0a, bu1a, bu0b, bu1b, bu_lsm + po + ko);
            #pragma unroll
            for (int mi = 0; mi < 4; mi++) {
                mma_f16(acg[mi][0], af[mi][0], af[mi][1], af[mi][2], af[mi][3], bg0a, bg1a);
                mma_f16(acg[mi][1], af[mi][0], af[mi][1], af[mi][2], af[mi][3], bg0b, bg1b);
                mma_f16(acu[mi][0], af[mi][0], af[mi][1], af[mi][2], af[mi][3], bu0a, bu1a);
                mma_f16(acu[mi][1], af[mi][0], af[mi][1], af[mi][2], af[mi][3], bu0b, bu1b);
            }
        }
        buf = (buf == NSTG - 1) ? 0 : buf + 1;
        pbuf = (pbuf == NSTG - 1) ? 0 : pbuf + 1;
    }

    const int q = lane >> 2, c2 = (lane & 3) * 2;
    #pragma unroll
    for (int mi = 0; mi < 4; mi++) {
        const int r0 = m0 + wm * 64 + mi * 16 + q;
        #pragma unroll
        for (int nj = 0; nj < 2; nj++) {
            const int col = cb + wn * 16 + nj * 8 + c2;
            if (r0 < cnt) {
                *(__half2*)(C + (size_t)r0 * ldc + col) =
                    __floats2half2_rn(silu_mul(acg[mi][nj][0], acu[mi][nj][0]),
                                      silu_mul(acg[mi][nj][1], acu[mi][nj][1]));
            }
            if (r0 + 8 < cnt) {
                *(__half2*)(C + (size_t)(r0 + 8) * ldc + col) =
                    __floats2half2_rn(silu_mul(acg[mi][nj][2], acu[mi][nj][2]),
                                      silu_mul(acg[mi][nj][3], acu[mi][nj][3]));
            }
        }
    }
}

// ================================================================
// GEMM 2 (fp16 + ldmatrix + 3-stage single-barrier pipeline)
// ================================================================
__global__ void __launch_bounds__(256, 2) mma_down_kernel(float* __restrict__ out) {
    const int z = blockIdx.z;
    const bool routed = z < E_;
    const int cnt = routed ? g_cnt[z] : T_;
    const int m0  = blockIdx.y * 128;
    if (m0 >= cnt) return;
    const int n0 = blockIdx.x * 128;

    const __half* A;
    const __half* W;
    int lda, ldw;
    if (routed) {
        A = g_inter + (size_t)z * T_ * INTER_; lda = INTER_;
        W = h_dp + (size_t)z * D_ * INTER_;    ldw = INTER_;
    } else {
        const int h = z - E_;
        A = g_hsh + (size_t)h * 512; lda = SH_INTER;
        W = h_sd  + (size_t)h * 512; ldw = SH_INTER;
    }

    extern __shared__ __half smem[];
    __half* As = smem;
    __half* Bs = smem + NSTG * PLANE;
    const uint32_t sA = smem_u32(As);
    const uint32_t sB = smem_u32(Bs);

    const int tid = threadIdx.x, wid = tid >> 5, lane = tid & 31;
    const int wm = wid >> 2, wn = wid & 3;

    const __half* agl[2]; const __half* bgl[2];
    uint32_t sa[2], sbo[2];
    #pragma unroll
    for (int t = 0; t < 2; t++) {
        int it = tid + 256 * t;
        int row = it >> 2, c4 = it & 3;
        int mm = m0 + row; if (mm > cnt - 1) mm = cnt - 1;
        agl[t] = A + (size_t)mm * lda + c4 * 8;
        bgl[t] = W + (size_t)(n0 + row) * ldw + c4 * 8;
        sa[t]  = sA + (uint32_t)(row * LDH + c4 * 8) * 2u;
        sbo[t] = sB + (uint32_t)(row * LDH + c4 * 8) * 2u;
    }

    const int alr = lane & 15, alk = (lane >> 4) * 8;
    const uint32_t a_lsm = sA + (uint32_t)(((wm * 64 + alr) * LDH) + alk) * 2u;
    const int bnr = ((lane >> 4) & 1) * 8 + (lane & 7), bkc = ((lane >> 3) & 1) * 8;
    const uint32_t b_lsm = sB + (uint32_t)(((wn * 32 + bnr) * LDH) + bkc) * 2u;

    float acc[4][4][4];
    #pragma unroll
    for (int mi = 0; mi < 4; mi++)
        #pragma unroll
        for (int nj = 0; nj < 4; nj++)
            #pragma unroll
            for (int r = 0; r < 4; r++) acc[mi][nj][r] = 0.f;

    const int NS = INTER_ / 32;   // 16 stages

    #pragma unroll
    for (int p = 0; p < 2; p++) {
        const uint32_t bo = (uint32_t)(p * ABYTES);
        #pragma unroll
        for (int t = 0; t < 2; t++) { cp16(sa[t] + bo, agl[t] + p * 32); cp16(sbo[t] + bo, bgl[t] + p * 32); }
        CP_COMMIT();
    }

    int buf = 0, pbuf = 2;
    for (int s = 0; s < NS; s++) {
        if (s + 1 < NS) CP_WAIT(1); else CP_WAIT(0);
        __syncthreads();
        if (s + 2 < NS) {
            const uint32_t bo = (uint32_t)(pbuf * ABYTES);
            #pragma unroll
            for (int t = 0; t < 2; t++) {
                cp16(sa[t] + bo, agl[t] + (s + 2) * 32);
                cp16(sbo[t] + bo, bgl[t] + (s + 2) * 32);
            }
            CP_COMMIT();
        }

        const uint32_t po = (uint32_t)(buf * ABYTES);
        #pragma unroll
        for (int ks = 0; ks < 2; ks++) {
            const uint32_t ko = (uint32_t)(ks * 32);
            uint32_t af[4][4];
            #pragma unroll
            for (int mi = 0; mi < 4; mi++)
                ldsm4(af[mi][0], af[mi][1], af[mi][2], af[mi][3],
                      a_lsm + po + ko + (uint32_t)(mi * 16 * LDH * 2));
            uint32_t b[4][2];
            ldsm4(b[0][0], b[0][1], b[1][0], b[1][1], b_lsm + po + ko);
            ldsm4(b[2][0], b[2][1], b[3][0], b[3][1], b_lsm + po + ko + (uint32_t)(16 * LDH * 2));
            #pragma unroll
            for (int nj = 0; nj < 4; nj++)
                #pragma unroll
                for (int mi = 0; mi < 4; mi++)
                    mma_f16(acc[mi][nj], af[mi][0], af[mi][1], af[mi][2], af[mi][3],
                            b[nj][0], b[nj][1]);
        }
        buf = (buf == NSTG - 1) ? 0 : buf + 1;
        pbuf = (pbuf == NSTG - 1) ? 0 : pbuf + 1;
    }

    const int q = lane >> 2, c2 = (lane & 3) * 2;
    #pragma unroll
    for (int mi = 0; mi < 4; mi++) {
        #pragma unroll
        for (int half_ = 0; half_ < 2; half_++) {
            const int m = m0 + wm * 64 + mi * 16 + q + half_ * 8;
            if (m >= cnt) continue;
            const int   tok = routed ? g_tok[z * T_ + m] : m;
            const float wt  = routed ? g_wt [z * T_ + m] : 1.f;
            float* op = out + (size_t)tok * D_;
            #pragma unroll
            for (int nj = 0; nj < 4; nj++) {
                const int col = n0 + wn * 32 + nj * 8 + c2;
                atomicAdd(op + col,     wt * acc[mi][nj][half_ * 2 + 0]);
                atomicAdd(op + col + 1, wt * acc[mi][nj][half_ * 2 + 1]);
            }
        }
    }
}

// ---------------- launch (stream-overlapped, graph-capturable fork/join) ----------------
extern "C" void kernel_launch(void* const* d_in, const int* in_sizes, int n_in,
                              void* d_out, int out_size) {
    const float* x  = (const float*)d_in[0];
    const float* gw = (const float*)d_in[2];
    const float* gb = (const float*)d_in[3];
    const float* gp = (const float*)d_in[4];
    const float* up = (const float*)d_in[5];
    const float* dp = (const float*)d_in[6];
    const float* sg = (const float*)d_in[7];
    const float* su = (const float*)d_in[8];
    const float* sd = (const float*)d_in[9];
    float* out = (float*)d_out;

    cudaFuncSetAttribute(mma_gu_kernel,   cudaFuncAttributeMaxDynamicSharedMemorySize, SMEM_BYTES);
    cudaFuncSetAttribute(mma_down_kernel, cudaFuncAttributeMaxDynamicSharedMemorySize, SMEM_BYTES);

    // per-call stream/event resources (host-side only; kernel_launch is invoked
    // a handful of times — correctness + capture — so this does not accumulate)
    cudaStream_t s1, s2;
    cudaStreamCreateWithFlags(&s1, cudaStreamNonBlocking);
    cudaStreamCreateWithFlags(&s2, cudaStreamNonBlocking);
    cudaEvent_t eF, e1, e2;
    cudaEventCreateWithFlags(&eF, cudaEventDisableTiming);
    cudaEventCreateWithFlags(&e1, cudaEventDisableTiming);
    cudaEventCreateWithFlags(&e2, cudaEventDisableTiming);

    const int NB = 256;

    // fork
    cudaEventRecord(eF, 0);
    cudaStreamWaitEvent(s1, eF, 0);
    cudaStreamWaitEvent(s2, eF, 0);

    // s1: down-side prep (runs under gu-side cvt + routing + gu GEMM)
    cudaMemsetAsync(out, 0, (size_t)T_ * D_ * sizeof(float), s1);
    cvt_dw_kernel<<<(DW8 + NB - 1) / NB, NB, 0, s1>>>(dp, sd);
    cudaEventRecord(e1, s1);

    // s2: routing (runs under gu-side cvt)
    zero_counts_kernel<<<1, 32, 0, s2>>>();
    route_kernel<<<T_, 128, 0, s2>>>(x, gw, gb);
    cudaEventRecord(e2, s2);

    // main stream: gu-side convert -> join routing -> gu -> join down-prep -> down
    cvt_guw_kernel<<<(GUW8 + NB - 1) / NB, NB>>>(gp, up, x, sg, su);
    cudaStreamWaitEvent(0, e2, 0);
    mma_gu_kernel<<<dim3(8, T_ / 128, NZ), 256, SMEM_BYTES>>>();
    cudaStreamWaitEvent(0, e1, 0);
    mma_down_kernel<<<dim3(D_ / 128, T_ / 128, NZ), 256, SMEM_BYTES>>>(out);

    cudaEventDestroy(eF);
    cudaEventDestroy(e1);
    cudaEventDestroy(e2);
    cudaStreamDestroy(s1);
    cudaStreamDestroy(s2);
}

// round 11
// speedup vs baseline: 1.4811x; 1.0183x over previous
#include <cuda_runtime.h>
#include <cuda_fp16.h>
#include <math.h>
#include <stdint.h>

// Problem constants
#define T_       1024
#define D_       1024
#define E_       16
#define K_SEL    4
#define NGRP     4
#define INTER_   512
#define SH_INTER 1024
#define RSCALE   2.5f

#define LDH   40                      // smem row stride in halves (80B, LDSM conflict-free)
#define PLANE (128 * LDH)             // halves per plane-stage
#define ABYTES (PLANE * 2)            // 10240 B
#define NSTG  3
#define SMEM_BYTES (2 * NSTG * ABYTES)   // 61440 B

// ---------------- device scratch (fp16 operands) ----------------
__device__ int    g_cnt[E_];
__device__ int    g_tok[E_ * T_];
__device__ float  g_wt [E_ * T_];
__device__ __half h_x [(size_t)T_ * D_];
__device__ __half h_gp[(size_t)E_ * INTER_ * D_];
__device__ __half h_up[(size_t)E_ * INTER_ * D_];
__device__ __half h_dp[(size_t)E_ * D_ * INTER_];
__device__ __half h_sg[(size_t)SH_INTER * D_];
__device__ __half h_su[(size_t)SH_INTER * D_];
__device__ __half h_sd[(size_t)D_ * SH_INTER];
__device__ __half g_inter[(size_t)E_ * T_ * INTER_];
__device__ __half g_hsh[(size_t)T_ * SH_INTER];

// ---------------- helpers ----------------
__device__ __forceinline__ uint32_t smem_u32(const void* p) {
    uint32_t a;
    asm("{ .reg .u64 t; cvta.to.shared.u64 t, %1; cvt.u32.u64 %0, t; }" : "=r"(a) : "l"(p));
    return a;
}
__device__ __forceinline__ void cp16(uint32_t s, const void* g) {
    asm volatile("cp.async.cg.shared.global [%0], [%1], 16;" :: "r"(s), "l"(g) : "memory");
}
#define CP_COMMIT() asm volatile("cp.async.commit_group;" ::: "memory")
#define CP_WAIT(n)  asm volatile("cp.async.wait_group %0;" :: "n"(n) : "memory")

__device__ __forceinline__ void ldsm4(uint32_t& r0, uint32_t& r1, uint32_t& r2, uint32_t& r3,
                                      uint32_t addr) {
    asm volatile("ldmatrix.sync.aligned.m8n8.x4.shared.b16 {%0,%1,%2,%3}, [%4];"
                 : "=r"(r0), "=r"(r1), "=r"(r2), "=r"(r3) : "r"(addr));
}
__device__ __forceinline__ void mma_f16(float c[4],
                                        uint32_t a0, uint32_t a1, uint32_t a2, uint32_t a3,
                                        uint32_t b0, uint32_t b1) {
    asm volatile(
        "mma.sync.aligned.m16n8k16.row.col.f32.f16.f16.f32 "
        "{%0,%1,%2,%3}, {%4,%5,%6,%7}, {%8,%9}, {%0,%1,%2,%3};"
        : "+f"(c[0]), "+f"(c[1]), "+f"(c[2]), "+f"(c[3])
        : "r"(a0), "r"(a1), "r"(a2), "r"(a3), "r"(b0), "r"(b1));
}
__device__ __forceinline__ float silu_mul(float g, float u) {
    return g / (1.f + expf(-g)) * u;
}

// ---------------- fused fp32 -> fp16 conversion ----------------
#define BIG8   (E_ * INTER_ * D_ / 8)
#define SML8   (SH_INTER * D_ / 8)

__device__ __forceinline__ void cvt_chunk(const float* s, __half* d, int i) {
    float4 v0 = ((const float4*)s)[2 * i];
    float4 v1 = ((const float4*)s)[2 * i + 1];
    ((__half2*)d)[4 * i + 0] = __floats2half2_rn(v0.x, v0.y);
    ((__half2*)d)[4 * i + 1] = __floats2half2_rn(v0.z, v0.w);
    ((__half2*)d)[4 * i + 2] = __floats2half2_rn(v1.x, v1.y);
    ((__half2*)d)[4 * i + 3] = __floats2half2_rn(v1.z, v1.w);
}

// routed gu-side: x, gp, up
#define GUX8 (SML8 + 2 * BIG8)
__global__ void cvt_gux_kernel(const float* __restrict__ x, const float* __restrict__ gp,
                               const float* __restrict__ up) {
    int i = blockIdx.x * blockDim.x + threadIdx.x;
    if (i >= GUX8) return;
    if (i < SML8)                  cvt_chunk(x,  h_x,  i);
    else if (i < SML8 + BIG8)      cvt_chunk(gp, h_gp, i - SML8);
    else                           cvt_chunk(up, h_up, i - SML8 - BIG8);
}
// shared gu-side: sg, su
__global__ void cvt_sgsu_kernel(const float* __restrict__ sg, const float* __restrict__ su) {
    int i = blockIdx.x * blockDim.x + threadIdx.x;
    if (i >= 2 * SML8) return;
    if (i < SML8) cvt_chunk(sg, h_sg, i);
    else          cvt_chunk(su, h_su, i - SML8);
}
// down-side: dp, sd
#define DW8 (BIG8 + SML8)
__global__ void cvt_dw_kernel(const float* __restrict__ dp, const float* __restrict__ sd) {
    int i = blockIdx.x * blockDim.x + threadIdx.x;
    if (i >= DW8) return;
    if (i < BIG8) cvt_chunk(dp, h_dp, i);
    else          cvt_chunk(sd, h_sd, i - BIG8);
}

// ---------------- routing ----------------
__global__ void zero_counts_kernel() {
    if (threadIdx.x < E_) g_cnt[threadIdx.x] = 0;
}

__global__ void route_kernel(const float* __restrict__ x,
                             const float* __restrict__ gw,
                             const float* __restrict__ gb) {
    const int t = blockIdx.x;
    __shared__ float xs[D_];
    __shared__ float sc[E_];
    const int tid = threadIdx.x;  // 128
    const float4* xr = (const float4*)(x + (size_t)t * D_);
    float4* xs4 = (float4*)xs;
    for (int i = tid; i < D_ / 4; i += 128) xs4[i] = xr[i];
    __syncthreads();

    const int warp = tid >> 5, lane = tid & 31;
    for (int e = warp * 4; e < warp * 4 + 4; e++) {
        const float* w = gw + (size_t)e * D_;
        float p = 0.f;
        for (int j = lane; j < D_; j += 32) p += xs[j] * w[j];
        #pragma unroll
        for (int o = 16; o; o >>= 1) p += __shfl_xor_sync(0xffffffffu, p, o);
        if (lane == 0) sc[e] = 1.f / (1.f + expf(-p));
    }
    __syncthreads();

    if (tid == 0) {
        float s[E_];
        #pragma unroll
        for (int e = 0; e < E_; e++) s[e] = sc[e] + gb[e];
        float gsc[NGRP];
        #pragma unroll
        for (int g = 0; g < NGRP; g++) {
            float m1 = -1e30f, m2 = -1e30f;
            #pragma unroll
            for (int j = 0; j < 4; j++) {
                float v = s[g * 4 + j];
                if (v > m1) { m2 = m1; m1 = v; } else if (v > m2) { m2 = v; }
            }
            gsc[g] = m1 + m2;
        }
        int g1 = 0;
        for (int g = 1; g < NGRP; g++) if (gsc[g] > gsc[g1]) g1 = g;
        int g2 = -1;
        for (int g = 0; g < NGRP; g++) {
            if (g == g1) continue;
            if (g2 < 0 || gsc[g] > gsc[g2]) g2 = g;
        }
        float masked[E_];
        #pragma unroll
        for (int e = 0; e < E_; e++) {
            int g = e >> 2;
            masked[e] = (g == g1 || g == g2) ? s[e] : 0.f;
        }
        int idx[K_SEL];
        float w[K_SEL];
        bool used[E_];
        #pragma unroll
        for (int e = 0; e < E_; e++) used[e] = false;
        float wsum = 0.f;
        for (int k = 0; k < K_SEL; k++) {
            int best = -1; float bv = -1e30f;
            for (int e = 0; e < E_; e++) {
                if (used[e]) continue;
                if (masked[e] > bv) { bv = masked[e]; best = e; }
            }
            used[best] = true;
            idx[k] = best;
            w[k] = sc[best];
            wsum += w[k];
        }
        const float scale = RSCALE / wsum;
        for (int k = 0; k < K_SEL; k++) {
            int e = idx[k];
            int pos = atomicAdd(&g_cnt[e], 1);
            g_tok[e * T_ + pos] = t;
            g_wt [e * T_ + pos] = w[k] * scale;
        }
    }
}

// ================================================================
// GEMM 1 (fp16 + ldmatrix + 3-stage single-barrier pipeline)
// zoff selects slice range: z < 16 routed expert, z >= 16 shared half.
// ================================================================
__global__ void __launch_bounds__(256, 2) mma_gu_kernel(int zoff) {
    const int z = zoff + blockIdx.z;
    const bool routed = z < E_;
    const int cnt = routed ? g_cnt[z] : T_;
    const int m0  = blockIdx.y * 128;
    if (m0 >= cnt) return;
    const int n0 = blockIdx.x * 64;

    const __half* Wg;
    const __half* Wu;
    __half* C;
    int ldc, cb;
    if (routed) {
        Wg = h_gp + ((size_t)z * INTER_ + n0) * D_;
        Wu = h_up + ((size_t)z * INTER_ + n0) * D_;
        C = g_inter + (size_t)z * T_ * INTER_;
        ldc = INTER_; cb = n0;
    } else {
        const int h = z - E_;
        Wg = h_sg + ((size_t)h * 512 + n0) * D_;
        Wu = h_su + ((size_t)h * 512 + n0) * D_;
        C = g_hsh;
        ldc = SH_INTER; cb = h * 512 + n0;
    }

    extern __shared__ __half smem[];
    __half* As = smem;
    __half* Bs = smem + NSTG * PLANE;
    const uint32_t sA = smem_u32(As);
    const uint32_t sB = smem_u32(Bs);

    const int tid = threadIdx.x, wid = tid >> 5, lane = tid & 31;
    const int wm = wid >> 2, wn = wid & 3;

    const __half* agl[2]; const __half* bgl[2];
    uint32_t sa[2], sbo[2];
    #pragma unroll
    for (int t = 0; t < 2; t++) {
        int it = tid + 256 * t;
        int row = it >> 2, c4 = it & 3;
        int mm = m0 + row; if (mm > cnt - 1) mm = cnt - 1;
        int ar = routed ? g_tok[z * T_ + mm] : mm;
        agl[t] = h_x + (size_t)ar * D_ + c4 * 8;
        bgl[t] = ((row < 64) ? (Wg + (size_t)row * D_) : (Wu + (size_t)(row - 64) * D_)) + c4 * 8;
        sa[t]  = sA + (uint32_t)(row * LDH + c4 * 8) * 2u;
        sbo[t] = sB + (uint32_t)(row * LDH + c4 * 8) * 2u;
    }

    const int alr = lane & 15, alk = (lane >> 4) * 8;
    const uint32_t a_lsm = sA + (uint32_t)(((wm * 64 + alr) * LDH) + alk) * 2u;
    const int bnr = ((lane >> 4) & 1) * 8 + (lane & 7), bkc = ((lane >> 3) & 1) * 8;
    const uint32_t bg_lsm = sB + (uint32_t)(((wn * 16 + bnr) * LDH) + bkc) * 2u;
    const uint32_t bu_lsm = sB + (uint32_t)(((wn * 16 + bnr + 64) * LDH) + bkc) * 2u;

    float acg[4][2][4], acu[4][2][4];
    #pragma unroll
    for (int mi = 0; mi < 4; mi++)
        #pragma unroll
        for (int nj = 0; nj < 2; nj++)
            #pragma unroll
            for (int r = 0; r < 4; r++) { acg[mi][nj][r] = 0.f; acu[mi][nj][r] = 0.f; }

    const int NS = D_ / 32;   // 32 stages

    #pragma unroll
    for (int p = 0; p < 2; p++) {
        const uint32_t bo = (uint32_t)(p * ABYTES);
        #pragma unroll
        for (int t = 0; t < 2; t++) { cp16(sa[t] + bo, agl[t] + p * 32); cp16(sbo[t] + bo, bgl[t] + p * 32); }
        CP_COMMIT();
    }

    int buf = 0, pbuf = 2;
    for (int s = 0; s < NS; s++) {
        if (s + 1 < NS) CP_WAIT(1); else CP_WAIT(0);
        __syncthreads();
        if (s + 2 < NS) {
            const uint32_t bo = (uint32_t)(pbuf * ABYTES);
            #pragma unroll
            for (int t = 0; t < 2; t++) {
                cp16(sa[t] + bo, agl[t] + (s + 2) * 32);
                cp16(sbo[t] + bo, bgl[t] + (s + 2) * 32);
            }
            CP_COMMIT();
        }

        const uint32_t po = (uint32_t)(buf * ABYTES);
        #pragma unroll
        for (int ks = 0; ks < 2; ks++) {
            const uint32_t ko = (uint32_t)(ks * 32);
            uint32_t af[4][4];
            #pragma unroll
            for (int mi = 0; mi < 4; mi++)
                ldsm4(af[mi][0], af[mi][1], af[mi][2], af[mi][3],
                      a_lsm + po + ko + (uint32_t)(mi * 16 * LDH * 2));
            uint32_t bg0a, bg1a, bg0b, bg1b, bu0a, bu1a, bu0b, bu1b;
            ldsm4(bg0a, bg1a, bg0b, bg1b, bg_lsm + po + ko);
            ldsm4(bu0a, bu1a, bu0b, bu1b, bu_lsm + po + ko);
            #pragma unroll
            for (int mi = 0; mi < 4; mi++) {
                mma_f16(acg[mi][0], af[mi][0], af[mi][1], af[mi][2], af[mi][3], bg0a, bg1a);
                mma_f16(acg[mi][1], af[mi][0], af[mi][1], af[mi][2], af[mi][3], bg0b, bg1b);
                mma_f16(acu[mi][0], af[mi][0], af[mi][1], af[mi][2], af[mi][3], bu0a, bu1a);
                mma_f16(acu[mi][1], af[mi][0], af[mi][1], af[mi][2], af[mi][3], bu0b, bu1b);
            }
        }
        buf = (buf == NSTG - 1) ? 0 : buf + 1;
        pbuf = (pbuf == NSTG - 1) ? 0 : pbuf + 1;
    }

    const int q = lane >> 2, c2 = (lane & 3) * 2;
    #pragma unroll
    for (int mi = 0; mi < 4; mi++) {
        const int r0 = m0 + wm * 64 + mi * 16 + q;
        #pragma unroll
        for (int nj = 0; nj < 2; nj++) {
            const int col = cb + wn * 16 + nj * 8 + c2;
            if (r0 < cnt) {
                *(__half2*)(C + (size_t)r0 * ldc + col) =
                    __floats2half2_rn(silu_mul(acg[mi][nj][0], acu[mi][nj][0]),
                                      silu_mul(acg[mi][nj][1], acu[mi][nj][1]));
            }
            if (r0 + 8 < cnt) {
                *(__half2*)(C + (size_t)(r0 + 8) * ldc + col) =
                    __floats2half2_rn(silu_mul(acg[mi][nj][2], acu[mi][nj][2]),
                                      silu_mul(acg[mi][nj][3], acu[mi][nj][3]));
            }
        }
    }
}

// ================================================================
// GEMM 2 (fp16 + ldmatrix + 3-stage single-barrier pipeline)
// ================================================================
__global__ void __launch_bounds__(256, 2) mma_down_kernel(int zoff, float* __restrict__ out) {
    const int z = zoff + blockIdx.z;
    const bool routed = z < E_;
    const int cnt = routed ? g_cnt[z] : T_;
    const int m0  = blockIdx.y * 128;
    if (m0 >= cnt) return;
    const int n0 = blockIdx.x * 128;

    const __half* A;
    const __half* W;
    int lda, ldw;
    if (routed) {
        A = g_inter + (size_t)z * T_ * INTER_; lda = INTER_;
        W = h_dp + (size_t)z * D_ * INTER_;    ldw = INTER_;
    } else {
        const int h = z - E_;
        A = g_hsh + (size_t)h * 512; lda = SH_INTER;
        W = h_sd  + (size_t)h * 512; ldw = SH_INTER;
    }

    extern __shared__ __half smem[];
    __half* As = smem;
    __half* Bs = smem + NSTG * PLANE;
    const uint32_t sA = smem_u32(As);
    const uint32_t sB = smem_u32(Bs);

    const int tid = threadIdx.x, wid = tid >> 5, lane = tid & 31;
    const int wm = wid >> 2, wn = wid & 3;

    const __half* agl[2]; const __half* bgl[2];
    uint32_t sa[2], sbo[2];
    #pragma unroll
    for (int t = 0; t < 2; t++) {
        int it = tid + 256 * t;
        int row = it >> 2, c4 = it & 3;
        int mm = m0 + row; if (mm > cnt - 1) mm = cnt - 1;
        agl[t] = A + (size_t)mm * lda + c4 * 8;
        bgl[t] = W + (size_t)(n0 + row) * ldw + c4 * 8;
        sa[t]  = sA + (uint32_t)(row * LDH + c4 * 8) * 2u;
        sbo[t] = sB + (uint32_t)(row * LDH + c4 * 8) * 2u;
    }

    const int alr = lane & 15, alk = (lane >> 4) * 8;
    const uint32_t a_lsm = sA + (uint32_t)(((wm * 64 + alr) * LDH) + alk) * 2u;
    const int bnr = ((lane >> 4) & 1) * 8 + (lane & 7), bkc = ((lane >> 3) & 1) * 8;
    const uint32_t b_lsm = sB + (uint32_t)(((wn * 32 + bnr) * LDH) + bkc) * 2u;

    float acc[4][4][4];
    #pragma unroll
    for (int mi = 0; mi < 4; mi++)
        #pragma unroll
        for (int nj = 0; nj < 4; nj++)
            #pragma unroll
            for (int r = 0; r < 4; r++) acc[mi][nj][r] = 0.f;

    const int NS = INTER_ / 32;   // 16 stages

    #pragma unroll
    for (int p = 0; p < 2; p++) {
        const uint32_t bo = (uint32_t)(p * ABYTES);
        #pragma unroll
        for (int t = 0; t < 2; t++) { cp16(sa[t] + bo, agl[t] + p * 32); cp16(sbo[t] + bo, bgl[t] + p * 32); }
        CP_COMMIT();
    }

    int buf = 0, pbuf = 2;
    for (int s = 0; s < NS; s++) {
        if (s + 1 < NS) CP_WAIT(1); else CP_WAIT(0);
        __syncthreads();
        if (s + 2 < NS) {
            const uint32_t bo = (uint32_t)(pbuf * ABYTES);
            #pragma unroll
            for (int t = 0; t < 2; t++) {
                cp16(sa[t] + bo, agl[t] + (s + 2) * 32);
                cp16(sbo[t] + bo, bgl[t] + (s + 2) * 32);
            }
            CP_COMMIT();
        }

        const uint32_t po = (uint32_t)(buf * ABYTES);
        #pragma unroll
        for (int ks = 0; ks < 2; ks++) {
            const uint32_t ko = (uint32_t)(ks * 32);
            uint32_t af[4][4];
            #pragma unroll
            for (int mi = 0; mi < 4; mi++)
                ldsm4(af[mi][0], af[mi][1], af[mi][2], af[mi][3],
                      a_lsm + po + ko + (uint32_t)(mi * 16 * LDH * 2));
            uint32_t b[4][2];
            ldsm4(b[0][0], b[0][1], b[1][0], b[1][1], b_lsm + po + ko);
            ldsm4(b[2][0], b[2][1], b[3][0], b[3][1], b_lsm + po + ko + (uint32_t)(16 * LDH * 2));
            #pragma unroll
            for (int nj = 0; nj < 4; nj++)
                #pragma unroll
                for (int mi = 0; mi < 4; mi++)
                    mma_f16(acc[mi][nj], af[mi][0], af[mi][1], af[mi][2], af[mi][3],
                            b[nj][0], b[nj][1]);
        }
        buf = (buf == NSTG - 1) ? 0 : buf + 1;
        pbuf = (pbuf == NSTG - 1) ? 0 : pbuf + 1;
    }

    const int q = lane >> 2, c2 = (lane & 3) * 2;
    #pragma unroll
    for (int mi = 0; mi < 4; mi++) {
        #pragma unroll
        for (int half_ = 0; half_ < 2; half_++) {
            const int m = m0 + wm * 64 + mi * 16 + q + half_ * 8;
            if (m >= cnt) continue;
            const int   tok = routed ? g_tok[z * T_ + m] : m;
            const float wt  = routed ? g_wt [z * T_ + m] : 1.f;
            float* op = out + (size_t)tok * D_;
            #pragma unroll
            for (int nj = 0; nj < 4; nj++) {
                const int col = n0 + wn * 32 + nj * 8 + c2;
                atomicAdd(op + col,     wt * acc[mi][nj][half_ * 2 + 0]);
                atomicAdd(op + col + 1, wt * acc[mi][nj][half_ * 2 + 1]);
            }
        }
    }
}

// ---------------- launch (dual-pipeline fork/join, graph-capturable) ----------------
extern "C" void kernel_launch(void* const* d_in, const int* in_sizes, int n_in,
                              void* d_out, int out_size) {
    const float* x  = (const float*)d_in[0];
    const float* gw = (const float*)d_in[2];
    const float* gb = (const float*)d_in[3];
    const float* gp = (const float*)d_in[4];
    const float* up = (const float*)d_in[5];
    const float* dp = (const float*)d_in[6];
    const float* sg = (const float*)d_in[7];
    const float* su = (const float*)d_in[8];
    const float* sd = (const float*)d_in[9];
    float* out = (float*)d_out;

    cudaFuncSetAttribute(mma_gu_kernel,   cudaFuncAttributeMaxDynamicSharedMemorySize, SMEM_BYTES);
    cudaFuncSetAttribute(mma_down_kernel, cudaFuncAttributeMaxDynamicSharedMemorySize, SMEM_BYTES);

    cudaStream_t s1, s2, s3;
    cudaStreamCreateWithFlags(&s1, cudaStreamNonBlocking);
    cudaStreamCreateWithFlags(&s2, cudaStreamNonBlocking);
    cudaStreamCreateWithFlags(&s3, cudaStreamNonBlocking);
    cudaEvent_t eF, eDW, eRoute, eGUX, eShared;
    cudaEventCreateWithFlags(&eF,     cudaEventDisableTiming);
    cudaEventCreateWithFlags(&eDW,    cudaEventDisableTiming);
    cudaEventCreateWithFlags(&eRoute, cudaEventDisableTiming);
    cudaEventCreateWithFlags(&eGUX,   cudaEventDisableTiming);
    cudaEventCreateWithFlags(&eShared,cudaEventDisableTiming);

    const int NB = 256;

    // fork
    cudaEventRecord(eF, 0);
    cudaStreamWaitEvent(s1, eF, 0);
    cudaStreamWaitEvent(s2, eF, 0);
    cudaStreamWaitEvent(s3, eF, 0);

    // s1: memset + down-side weight convert (hidden under gu stage)
    cudaMemsetAsync(out, 0, (size_t)T_ * D_ * sizeof(float), s1);
    cvt_dw_kernel<<<(DW8 + NB - 1) / NB, NB, 0, s1>>>(dp, sd);
    cudaEventRecord(eDW, s1);

    // s2: routing (hidden under gu-side convert)
    zero_counts_kernel<<<1, 32, 0, s2>>>();
    route_kernel<<<T_, 128, 0, s2>>>(x, gw, gb);
    cudaEventRecord(eRoute, s2);

    // s0 (capture stream): routed pipeline
    cvt_gux_kernel<<<(GUX8 + NB - 1) / NB, NB>>>(x, gp, up);
    cudaEventRecord(eGUX, 0);
    cudaStreamWaitEvent(0, eRoute, 0);
    mma_gu_kernel<<<dim3(INTER_ / 64, T_ / 128, E_), 256, SMEM_BYTES>>>(0);
    cudaStreamWaitEvent(0, eDW, 0);
    mma_down_kernel<<<dim3(D_ / 128, T_ / 128, E_), 256, SMEM_BYTES>>>(0, out);

    // s3: shared pipeline (concurrent with routed pipeline)
    cvt_sgsu_kernel<<<(2 * SML8 + NB - 1) / NB, NB, 0, s3>>>(sg, su);
    cudaStreamWaitEvent(s3, eGUX, 0);                // needs converted x
    mma_gu_kernel<<<dim3(8, T_ / 128, 2), 256, SMEM_BYTES, s3>>>(E_);
    cudaStreamWaitEvent(s3, eDW, 0);                 // needs sd + memset
    mma_down_kernel<<<dim3(D_ / 128, T_ / 128, 2), 256, SMEM_BYTES, s3>>>(E_, out);
    cudaEventRecord(eShared, s3);

    // join shared pipeline back into capture stream
    cudaStreamWaitEvent(0, eShared, 0);

    cudaEventDestroy(eF);
    cudaEventDestroy(eDW);
    cudaEventDestroy(eRoute);
    cudaEventDestroy(eGUX);
    cudaEventDestroy(eShared);
    cudaStreamDestroy(s1);
    cudaStreamDestroy(s2);
    cudaStreamDestroy(s3);
}